// round 15
// baseline (speedup 1.0000x reference)
#include <cuda_runtime.h>

// MANN_Attn R13 (resubmit after infra failure): exact R9 + fused wr-softmax/
// readout (I+J) in dec tail.
//  CTAs 0..31 enc0 (NB=2), 32..63 enc1, 64..95 dec (NB=2), pipelined flags.

typedef unsigned long long u64;

static __device__ float g_o1[16 * 64 * 32 * 64]; // [t][b][l][e]
static __device__ float g_o2[16 * 64 * 32 * 64];
static __device__ __align__(16) float g_wi_pad[128 * 516];
static __device__ __align__(16) float g_outw_pad[256 * 156];
static __device__ __align__(16) float g_tbl[153 * 128];
static __device__ int g_prog[64];

__device__ __forceinline__ float sigf(float x) { return 1.0f / (1.0f + expf(-x)); }
__device__ __forceinline__ float softplusf(float x) { return (x > 15.0f) ? x : log1pf(expf(x)); }
__device__ __forceinline__ u64 bc2(float w) {
    u64 r; asm("mov.b64 %0, {%1, %1};" : "=l"(r) : "f"(w)); return r;
}
__device__ __forceinline__ void fma2(u64& a, u64 w, u64 x) {
    asm("fma.rn.f32x2 %0, %1, %2, %0;" : "+l"(a) : "l"(w), "l"(x));
}
#define BARX() asm volatile("bar.sync 1, 384;" ::: "memory")

__global__ void prep_kernel(const float* __restrict__ wi, const float* __restrict__ outw,
                            const float* __restrict__ emb2, const float* __restrict__ combw)
{
    int i = blockIdx.x * 256 + threadIdx.x;
    if (i < 64) g_prog[i] = 0;
    if (i < 128 * 516) { int k = i / 516, j = i % 516; g_wi_pad[i] = (j < 515) ? wi[k * 515 + j] : 0.f; }
    if (i < 256 * 156) { int k = i / 156, j = i % 156; g_outw_pad[i] = (j < 153) ? outw[k * 153 + j] : 0.f; }
    if (i < 153 * 128) {
        int t = i / 128, j = i % 128;
        float a = 0.f;
        #pragma unroll 8
        for (int e = 0; e < 64; e++) a += emb2[t * 64 + e] * combw[e * 128 + j];
        g_tbl[i] = a;
    }
}

struct EncP {
    const int* codes; const float* emb;
    const float *wx, *wh, *bx, *bh, *wi, *bi;
};
struct DecP {
    const int* targets;
    const float *wx, *wh, *bx, *bh, *bi;
    const float *attn0, *attn1, *combw, *combb, *outb;
    float* out;
};

// ---------------- Encoder body (R9, NB=2, wx from L2) ----------------
__device__ void enc_body(const EncP& p, float* o_out, int b0, float* sm)
{
    const int tid = threadIdx.x;
    float* s_wh = sm;               // 12288 (64x192)
    float* s_wi = s_wh + 12288;     // 16640 (64x260 padded)
    float* s_bx = s_wi + 16640;     // 192
    float* s_bh = s_bx + 192;       // 192
    float* s_bi = s_bh + 192;       // 260
    float* s_p  = s_bi + 260;       // 7680 partial union
    float* s_x  = s_p + 7680;       // 256 [k][b]  (x|r)
    float* s_h  = s_x + 256;        // 128 [j][b]
    float* s_gx = s_h + 128;        // 384
    float* s_gh = s_gx + 384;       // 384
    float* s_if = s_gh + 384;       // 520
    float* s_M  = s_if + 520;       // 2048 [b][n][e]
    float* s_mn = s_M + 2048;       // 32
    float* s_md = s_mn + 32;        // 32
    float* s_w  = s_md + 32;        // 32
    float* s_kn = s_w + 32;         // 8

    float* p_gx = s_p;              // 16 x 384
    float* p_gh = s_p + 6144;       // 4 x 384
    float* p_if = s_p;              // 8 x 520 (reuse)

    for (int i = tid; i < 12288; i += 768) s_wh[i] = p.wh[i];
    for (int i = tid; i < 16640; i += 768) {
        int k = i / 260, j = i % 260;
        s_wi[i] = (j < 259) ? p.wi[k * 259 + j] : 0.f;
    }
    if (tid < 192) { s_bx[tid] = p.bx[tid]; s_bh[tid] = p.bh[tid]; }
    if (tid < 260) s_bi[tid] = (tid < 259) ? p.bi[tid] : 0.f;
    if (tid < 256) s_x[tid] = 0.f;
    if (tid < 128) s_h[tid] = 0.f;
    for (int i = tid; i < 2048; i += 768) s_M[i] = 0.f;
    for (int i = tid; i < 1536; i += 768) p_gh[i] = 0.f;
    __syncthreads();

    const int c8 = tid & 7;
    const int pq = tid >> 3;
    const int pb = pq >> 4;
    float* Mp = s_M + pq * 64 + c8 * 8;

    if (tid < 128) {
        int b = tid & 1, e = tid >> 1;
        int code = p.codes[(b0 + b) * 512 + 0];
        s_x[e * 2 + b] = p.emb[code * 64 + e];
    }
    __syncthreads();

    for (int s = 0; s < 512; ++s) {
        // B: gx partials (wx from L2): 48 jq x 16 kq = 768 threads, 8 iters
        {
            int jq = tid % 48, kq = tid / 48;
            u64 a0 = 0, a1 = 0, a2 = 0, a3 = 0;
            const float* wb = p.wx + kq * 8 * 192 + jq * 4;
            const u64* xb = (const u64*)(s_x + kq * 16);
            #pragma unroll
            for (int i = 0; i < 8; i++) {
                float4 w = __ldg((const float4*)(wb + i * 192));
                u64 x2 = xb[i];
                fma2(a0, bc2(w.x), x2); fma2(a1, bc2(w.y), x2);
                fma2(a2, bc2(w.z), x2); fma2(a3, bc2(w.w), x2);
            }
            u64* d = (u64*)(p_gx + kq * 384 + jq * 8);
            d[0] = a0; d[1] = a1; d[2] = a2; d[3] = a3;
        }
        __syncthreads();
        // C: reduce gx (384) + gh (384)
        if (tid < 384) {
            float a = s_bx[tid >> 1];
            #pragma unroll
            for (int kq = 0; kq < 16; kq++) a += p_gx[kq * 384 + tid];
            s_gx[tid] = a;
        } else {
            int u = tid - 384;
            float g = s_bh[u >> 1];
            #pragma unroll
            for (int kh = 0; kh < 4; kh++) g += p_gh[kh * 384 + u];
            s_gh[u] = g;
        }
        __syncthreads();
        // GRU
        if (tid < 128) {
            int b = tid & 1, j = tid >> 1;
            float xr = s_gx[j*2+b], xz = s_gx[(64+j)*2+b], xn = s_gx[(128+j)*2+b];
            float hr = s_gh[j*2+b], hz = s_gh[(64+j)*2+b], hn = s_gh[(128+j)*2+b];
            float rg = sigf(xr + hr), z = sigf(xz + hz);
            float n = tanhf(xn + rg * hn);
            s_h[j*2+b] = (1.0f - z) * n + z * s_h[j*2+b];
        }
        __syncthreads();
        // iface partials: 65 jq x 8 kq = 520 threads, 8 iters
        if (tid < 520) {
            int jq = tid % 65, kq = tid / 65;
            u64 a0 = 0, a1 = 0, a2 = 0, a3 = 0;
            const float* wb = s_wi + kq * 8 * 260 + jq * 4;
            const u64* xb = (const u64*)(s_h + kq * 16);
            #pragma unroll
            for (int i = 0; i < 8; i++) {
                float4 w = *(const float4*)(wb + i * 260);
                u64 x2 = xb[i];
                fma2(a0, bc2(w.x), x2); fma2(a1, bc2(w.y), x2);
                fma2(a2, bc2(w.z), x2); fma2(a3, bc2(w.w), x2);
            }
            u64* d = (u64*)(p_if + kq * 520 + jq * 8);
            d[0] = a0; d[1] = a1; d[2] = a2; d[3] = a3;
        }
        __syncthreads();
        if (tid < 520) {
            float a = s_bi[tid >> 1];
            #pragma unroll
            for (int kq = 0; kq < 8; kq++) a += p_if[kq * 520 + tid];
            s_if[tid] = a;
        }
        __syncthreads();

        if (s < 511) {
            if (tid < 384) {
                if (tid < 256) {
                    float ss = 0.f, dw = 0.f;
                    #pragma unroll
                    for (int i = 0; i < 8; i++) {
                        float m = Mp[i];
                        ss += m * m; dw += m * s_if[(64 + c8 * 8 + i) * 2 + pb];
                    }
                    for (int d = 4; d > 0; d >>= 1) {
                        ss += __shfl_down_sync(0xffffffffu, ss, d);
                        dw += __shfl_down_sync(0xffffffffu, dw, d);
                    }
                    if (c8 == 0) { s_mn[pq] = sqrtf(ss); s_md[pq] = dw; }
                } else {
                    int w = (tid >> 5) - 8, lane = tid & 31;
                    int b = w & 1, isr = w >> 1;
                    int base = isr ? 0 : 64;
                    float v0 = s_if[(base + lane) * 2 + b], v1 = s_if[(base + 32 + lane) * 2 + b];
                    float t2 = v0 * v0 + v1 * v1;
                    for (int d = 16; d > 0; d >>= 1) t2 += __shfl_down_sync(0xffffffffu, t2, d);
                    if (lane == 0) s_kn[isr * 2 + b] = sqrtf(t2);
                }
                BARX();
                if (tid < 64 && (tid & 31) < 16) {
                    int b = tid >> 5, n = tid & 15;
                    float bw = softplusf(s_if[257*2+b]) + 1.0f;
                    float gw = sigf(s_if[258*2+b]);
                    float kn = s_kn[0*2+b];
                    float sc = bw * (s_md[b*16+n] / (s_mn[b*16+n] * kn + 1e-6f));
                    float mx = sc;
                    for (int d = 8; d > 0; d >>= 1) mx = fmaxf(mx, __shfl_xor_sync(0xffffu, mx, d));
                    float e = expf(sc - mx);
                    float sum = e;
                    for (int d = 8; d > 0; d >>= 1) sum += __shfl_xor_sync(0xffffu, sum, d);
                    s_w[b*16+n] = e * (gw / sum);
                }
                BARX();
                if (tid < 256) {
                    float wwv = s_w[pq], ss = 0.f, dr = 0.f;
                    #pragma unroll
                    for (int i = 0; i < 8; i++) {
                        int e = c8 * 8 + i;
                        float er = sigf(s_if[(128 + e) * 2 + pb]);
                        float wv = s_if[(192 + e) * 2 + pb];
                        float m = Mp[i];
                        m = m * (1.0f - wwv * er) + wwv * wv;
                        Mp[i] = m;
                        ss += m * m; dr += m * s_if[e * 2 + pb];
                    }
                    for (int d = 4; d > 0; d >>= 1) {
                        ss += __shfl_down_sync(0xffffffffu, ss, d);
                        dr += __shfl_down_sync(0xffffffffu, dr, d);
                    }
                    if (c8 == 0) { s_mn[pq] = sqrtf(ss); s_md[pq] = dr; }
                }
                BARX();
                if (tid < 64 && (tid & 31) < 16) {
                    int b = tid >> 5, n = tid & 15;
                    float br = softplusf(s_if[256*2+b]) + 1.0f;
                    float kn = s_kn[1*2+b];
                    float sc = br * (s_md[b*16+n] / (s_mn[b*16+n] * kn + 1e-6f));
                    float mx = sc;
                    for (int d = 8; d > 0; d >>= 1) mx = fmaxf(mx, __shfl_xor_sync(0xffffu, mx, d));
                    float e = expf(sc - mx);
                    float sum = e;
                    for (int d = 8; d > 0; d >>= 1) sum += __shfl_xor_sync(0xffffu, sum, d);
                    s_w[b*16+n] = e / sum;
                }
                BARX();
                if (tid < 128) {
                    int b = tid & 1, e = tid >> 1;
                    const float* Mb = s_M + b * 1024;
                    float r = 0.f;
                    #pragma unroll
                    for (int n = 0; n < 16; n++) r += s_w[b*16+n] * Mb[n * 64 + e];
                    s_x[(64 + e) * 2 + b] = r;
                    o_out[(((s >> 5) * 64 + (b0 + b)) * 32 + (s & 31)) * 64 + e] = s_h[e * 2 + b];
                }
            } else if (tid < 576) {
                int u = tid - 384;
                int jq = u % 48, kh = u / 48;
                u64 a0 = 0, a1 = 0, a2 = 0, a3 = 0;
                const float* wb = s_wh + kh * 16 * 192 + jq * 4;
                const u64* xb = (const u64*)(s_h + kh * 32);
                #pragma unroll
                for (int i = 0; i < 16; i++) {
                    float4 w = *(const float4*)(wb + i * 192);
                    u64 x2 = xb[i];
                    fma2(a0, bc2(w.x), x2); fma2(a1, bc2(w.y), x2);
                    fma2(a2, bc2(w.z), x2); fma2(a3, bc2(w.w), x2);
                }
                u64* d = (u64*)(p_gh + kh * 384 + jq * 8);
                d[0] = a0; d[1] = a1; d[2] = a2; d[3] = a3;
            } else if (tid < 704) {
                int u = tid - 576;
                int b = u & 1, e = u >> 1;
                int code = p.codes[(b0 + b) * 512 + (s + 1)];
                s_x[e * 2 + b] = p.emb[code * 64 + e];
            }
            __syncthreads();
        } else {
            if (tid < 128) {
                int b = tid & 1, e = tid >> 1;
                o_out[(((s >> 5) * 64 + (b0 + b)) * 32 + (s & 31)) * 64 + e] = s_h[e * 2 + b];
            }
            __syncthreads();
        }
        if ((s & 31) == 31) {
            __threadfence();
            if (tid == 0) atomicExch(&g_prog[blockIdx.x], (s >> 5) + 1);
        }
    }
}

// ---------------- Decoder body (R9 + fused I+J tail) ----------------
__device__ void dec_body(const DecP& p, int jj, float* sm)
{
    const int b0 = jj * 2;
    const int tid = threadIdx.x;

    float* s_ow = sm;            // 19968 (128x156) outw h-half cache
    float* s_p  = s_ow + 19968;  // 12288 partial union
    float* s_x  = s_p + 12288;   // 512
    float* s_h  = s_x + 512;     // 256
    float* s_gx = s_h + 256;     // 768
    float* s_gh = s_gx + 768;    // 768
    float* s_if = s_gh + 768;    // 1032
    float* s_M  = s_if + 1032;   // 4096
    float* s_c  = s_M + 4096;    // 256
    float* s_cc = s_c + 256;     // 256
    float* s_oc = s_cc + 256;    // 312
    float* s_at = s_oc + 312;    // 128
    float* s_mn = s_at + 128;    // 32
    float* s_md = s_mn + 32;     // 32
    float* s_w  = s_md + 32;     // 32
    float* s_kn = s_w + 32;      // 8
    float* s_bx2 = s_kn + 8;     // 384
    float* s_bh2 = s_bx2 + 384;  // 384
    float* s_bi2 = s_bh2 + 384;  // 520

    float* p_wx = s_p;           // 8 x 768
    float* p_wh = s_p + 6144;    // 4 x 768
    float* p_if = s_p;           // 4 x 1032
    float* p_oh = s_p + 4224;    // 4 x 312
    float* p_cb = s_p;           // 4 x 256 (per-v)
    float* p_oc = s_p + 1024;    // 4 x 312 (per-v)

    for (int i = tid; i < 19968; i += 768) s_ow[i] = g_outw_pad[i];
    for (int i = tid; i < 512; i += 768) s_x[i] = 0.f;
    for (int i = tid; i < 4096; i += 768) s_M[i] = 0.f;
    if (tid < 384) { s_bx2[tid] = p.bx[tid]; s_bh2[tid] = p.bh[tid]; }
    if (tid < 520) s_bi2[tid] = (tid < 515) ? p.bi[tid] : 0.f;
    __syncthreads();

    if (tid == 0) {
        while (*(volatile int*)&g_prog[jj] < 1 || *(volatile int*)&g_prog[32 + jj] < 1)
            __nanosleep(200);
    }
    __syncthreads();
    if (tid < 256) {
        int b = tid & 1, e = tid >> 1;
        float h = (e < 64) ? g_o1[((b0 + b) * 32 + 31) * 64 + e]
                           : g_o2[((b0 + b) * 32 + 31) * 64 + (e - 64)];
        s_h[e * 2 + b] = h;
    }
    __syncthreads();

    const int c8 = tid & 7;
    const int pq = tid >> 3;
    const int pb = pq >> 4;
    float* Mp = s_M + pq * 128 + c8 * 16;

    for (int s = 0; s < 400; ++s) {
        const int v = s / 25, pos = s - v * 25;

        if (pos == 0) {
            if (tid == 0) {
                while (*(volatile int*)&g_prog[jj] <= v || *(volatile int*)&g_prog[32 + jj] <= v)
                    __nanosleep(200);
            }
            __syncthreads();
            // V0: attention scores
            if (tid < 256) {
                int cc = tid & 1, g = tid >> 1;
                int a = g >> 6, b = (g >> 5) & 1, l = g & 31;
                const float* op = (a ? g_o2 : g_o1) + ((v * 64 + (b0 + b)) * 32 + l) * 64 + cc * 32;
                const float* aw = (a ? p.attn1 : p.attn0) + 128 + cc * 32;
                float sc = 0.f;
                #pragma unroll
                for (int e = 0; e < 32; e++) sc += op[e] * __ldg(aw + e);
                sc += __shfl_down_sync(0xffffffffu, sc, 1);
                if (cc == 0) s_at[g] = sc;
            }
            __syncthreads();
            // V1: softmax
            if (tid < 128) {
                int w = tid >> 5, l = tid & 31;
                float vsc = s_at[w * 32 + l];
                float mx = vsc;
                for (int d = 16; d > 0; d >>= 1) mx = fmaxf(mx, __shfl_xor_sync(0xffffffffu, mx, d));
                float e2 = expf(vsc - mx);
                float sum = e2;
                for (int d = 16; d > 0; d >>= 1) sum += __shfl_xor_sync(0xffffffffu, sum, d);
                s_at[w * 32 + l] = e2 / sum;
            }
            __syncthreads();
            // V2: contexts
            if (tid < 256) {
                int a = tid >> 7, b = (tid >> 6) & 1, e = tid & 63;
                const float* op = (a ? g_o2 : g_o1) + ((v * 64 + (b0 + b)) * 32) * 64 + e;
                const float* at = s_at + a * 64 + b * 32;
                float cv = 0.f;
                #pragma unroll
                for (int l = 0; l < 32; l++) cv += at[l] * op[l * 64];
                s_c[(a * 64 + e) * 2 + b] = cv;
            }
            __syncthreads();
            // V3: comb_cc + out_cc partials
            if (tid < 128) {
                int jq = tid & 31, kq = tid >> 5;
                u64 a0 = 0, a1 = 0, a2 = 0, a3 = 0;
                const float* wb = p.combw + (64 + kq * 32) * 128 + jq * 4;
                const u64* xb = (const u64*)(s_c + kq * 64);
                #pragma unroll
                for (int i = 0; i < 32; i++) {
                    float4 w = __ldg((const float4*)(wb + i * 128));
                    u64 x2 = xb[i];
                    fma2(a0, bc2(w.x), x2); fma2(a1, bc2(w.y), x2);
                    fma2(a2, bc2(w.z), x2); fma2(a3, bc2(w.w), x2);
                }
                u64* d = (u64*)(p_cb + kq * 256 + jq * 8);
                d[0] = a0; d[1] = a1; d[2] = a2; d[3] = a3;
            } else if (tid < 284) {
                int u = tid - 128;
                int jq = u % 39, kq = u / 39;
                u64 a0 = 0, a1 = 0, a2 = 0, a3 = 0;
                const float* wb = g_outw_pad + (128 + kq * 32) * 156 + jq * 4;
                const u64* xb = (const u64*)(s_c + kq * 64);
                #pragma unroll
                for (int i = 0; i < 32; i++) {
                    float4 w = __ldg((const float4*)(wb + i * 156));
                    u64 x2 = xb[i];
                    fma2(a0, bc2(w.x), x2); fma2(a1, bc2(w.y), x2);
                    fma2(a2, bc2(w.z), x2); fma2(a3, bc2(w.w), x2);
                }
                u64* d = (u64*)(p_oc + kq * 312 + jq * 8);
                d[0] = a0; d[1] = a1; d[2] = a2; d[3] = a3;
            }
            __syncthreads();
            // V4: reduce
            if (tid < 256) {
                float a = __ldg(p.combb + (tid >> 1));
                #pragma unroll
                for (int kq = 0; kq < 4; kq++) a += p_cb[kq * 256 + tid];
                s_cc[tid] = a;
            } else if (tid < 568) {
                int idx = tid - 256;
                int j = idx >> 1;
                float a = (j < 153) ? __ldg(p.outb + j) : 0.f;
                #pragma unroll
                for (int kq = 0; kq < 4; kq++) a += p_oc[kq * 312 + idx];
                s_oc[idx] = a;
            }
            __syncthreads();
            // A-inline: comb (start/split token) + wh partials
            if (tid < 256) {
                int tok = (v == 0) ? 150 : 151;
                s_x[tid] = fmaxf(__ldg(g_tbl + tok * 128 + (tid >> 1)) + s_cc[tid], 0.f);
            } else if (tid < 640) {
                int u = tid - 256;
                int jq = u % 96, kq = u / 96;
                u64 a0 = 0, a1 = 0, a2 = 0, a3 = 0;
                const float* wb = p.wh + kq * 32 * 384 + jq * 4;
                const u64* xb = (const u64*)(s_h + kq * 64);
                #pragma unroll
                for (int i = 0; i < 32; i++) {
                    float4 w = __ldg((const float4*)(wb + i * 384));
                    u64 x2 = xb[i];
                    fma2(a0, bc2(w.x), x2); fma2(a1, bc2(w.y), x2);
                    fma2(a2, bc2(w.z), x2); fma2(a3, bc2(w.w), x2);
                }
                u64* d = (u64*)(p_wh + kq * 768 + jq * 8);
                d[0] = a0; d[1] = a1; d[2] = a2; d[3] = a3;
            }
            __syncthreads();
        }

        // B: wx partials: 96 jq x 8 kq = 768 threads, 32 iters
        {
            int jq = tid % 96, kq = tid / 96;
            u64 a0 = 0, a1 = 0, a2 = 0, a3 = 0;
            const float* wb = p.wx + kq * 32 * 384 + jq * 4;
            const u64* xb = (const u64*)(s_x + kq * 64);
            #pragma unroll
            for (int i = 0; i < 32; i++) {
                float4 w = __ldg((const float4*)(wb + i * 384));
                u64 x2 = xb[i];
                fma2(a0, bc2(w.x), x2); fma2(a1, bc2(w.y), x2);
                fma2(a2, bc2(w.z), x2); fma2(a3, bc2(w.w), x2);
            }
            u64* d = (u64*)(p_wx + kq * 768 + jq * 8);
            d[0] = a0; d[1] = a1; d[2] = a2; d[3] = a3;
        }
        __syncthreads();
        // C1: reduce gx/gh
        {
            float a = s_bx2[tid >> 1];
            float g = s_bh2[tid >> 1];
            #pragma unroll
            for (int kq = 0; kq < 8; kq++) a += p_wx[kq * 768 + tid];
            #pragma unroll
            for (int kq = 0; kq < 4; kq++) g += p_wh[kq * 768 + tid];
            s_gx[tid] = a; s_gh[tid] = g;
        }
        __syncthreads();
        // C2: GRU
        if (tid < 256) {
            int b = tid & 1, j = tid >> 1;
            float xr = s_gx[j*2+b], xz = s_gx[(128+j)*2+b], xn = s_gx[(256+j)*2+b];
            float hr = s_gh[j*2+b], hz = s_gh[(128+j)*2+b], hn = s_gh[(256+j)*2+b];
            float rg = sigf(xr + hr), z = sigf(xz + hz);
            float n = tanhf(xn + rg * hn);
            s_h[j*2+b] = (1.0f - z) * n + z * s_h[j*2+b];
        }
        __syncthreads();
        // D: wi (L2) + outw_h (smem) partials
        if (tid < 516) {
            int jq = tid % 129, kq = tid / 129;
            u64 a0 = 0, a1 = 0, a2 = 0, a3 = 0;
            const float* wb = g_wi_pad + kq * 32 * 516 + jq * 4;
            const u64* xb = (const u64*)(s_h + kq * 64);
            #pragma unroll
            for (int i = 0; i < 32; i++) {
                float4 w = *(const float4*)(wb + i * 516);
                u64 x2 = xb[i];
                fma2(a0, bc2(w.x), x2); fma2(a1, bc2(w.y), x2);
                fma2(a2, bc2(w.z), x2); fma2(a3, bc2(w.w), x2);
            }
            u64* d = (u64*)(p_if + kq * 1032 + jq * 8);
            d[0] = a0; d[1] = a1; d[2] = a2; d[3] = a3;
        } else if (tid < 672) {
            int u = tid - 516;
            int jq = u % 39, kq = u / 39;
            u64 a0 = 0, a1 = 0, a2 = 0, a3 = 0;
            const float* wb = s_ow + kq * 32 * 156 + jq * 4;
            const u64* xb = (const u64*)(s_h + kq * 64);
            #pragma unroll
            for (int i = 0; i < 32; i++) {
                float4 w = *(const float4*)(wb + i * 156);
                u64 x2 = xb[i];
                fma2(a0, bc2(w.x), x2); fma2(a1, bc2(w.y), x2);
                fma2(a2, bc2(w.z), x2); fma2(a3, bc2(w.w), x2);
            }
            u64* d = (u64*)(p_oh + kq * 312 + jq * 8);
            d[0] = a0; d[1] = a1; d[2] = a2; d[3] = a3;
        }
        __syncthreads();
        // E: reduce iface + logits store
        for (int u = tid; u < 1030; u += 768) {
            float a = s_bi2[u >> 1];
            #pragma unroll
            for (int kq = 0; kq < 4; kq++) a += p_if[kq * 1032 + u];
            s_if[u] = a;
        }
        if (tid < 306) {
            int j = tid >> 1, b = tid & 1;
            float a = s_oc[tid];
            #pragma unroll
            for (int kq = 0; kq < 4; kq++) a += p_oh[kq * 312 + tid];
            p.out[((b0 + b) * 400 + s) * 153 + j] = a;
        }
        __syncthreads();

        if (pos < 24) {
            if (tid < 384) {
                // F: stats + key norms
                if (tid < 256) {
                    float ss = 0.f, dw = 0.f;
                    #pragma unroll
                    for (int i = 0; i < 16; i++) {
                        float m = Mp[i];
                        ss += m * m; dw += m * s_if[(128 + c8 * 16 + i) * 2 + pb];
                    }
                    for (int d = 4; d > 0; d >>= 1) {
                        ss += __shfl_down_sync(0xffffffffu, ss, d);
                        dw += __shfl_down_sync(0xffffffffu, dw, d);
                    }
                    if (c8 == 0) { s_mn[pq] = sqrtf(ss); s_md[pq] = dw; }
                } else {
                    int w = (tid >> 5) - 8, lane = tid & 31;
                    int b = w & 1, isr = w >> 1;
                    int base = isr ? 0 : 128;
                    float t2 = 0.f;
                    #pragma unroll
                    for (int q = 0; q < 4; q++) {
                        float vq = s_if[(base + lane + q * 32) * 2 + b];
                        t2 += vq * vq;
                    }
                    for (int d = 16; d > 0; d >>= 1) t2 += __shfl_down_sync(0xffffffffu, t2, d);
                    if (lane == 0) s_kn[isr * 2 + b] = sqrtf(t2);
                }
                BARX();
                // G: ww softmax + next comb
                if (tid < 64) {
                    if ((tid & 31) < 16) {
                        int b = tid >> 5, n = tid & 15;
                        float bw = softplusf(s_if[513*2+b]) + 1.0f;
                        float gw = sigf(s_if[514*2+b]);
                        float kn = s_kn[0*2+b];
                        float sc = bw * (s_md[b*16+n] / (s_mn[b*16+n] * kn + 1e-6f));
                        float mx = sc;
                        for (int d = 8; d > 0; d >>= 1) mx = fmaxf(mx, __shfl_xor_sync(0xffffu, mx, d));
                        float e = expf(sc - mx);
                        float sum = e;
                        for (int d = 8; d > 0; d >>= 1) sum += __shfl_xor_sync(0xffffu, sum, d);
                        s_w[b*16+n] = e * (gw / sum);
                    }
                } else if (tid < 320) {
                    int idx = tid - 64;
                    int b = idx & 1, j = idx >> 1;
                    int tok = p.targets[((b0 + b) * 16 + v) * 24 + pos];
                    s_x[idx] = fmaxf(__ldg(g_tbl + tok * 128 + j) + s_cc[idx], 0.f);
                }
                BARX();
                // H: M update + post stats
                if (tid < 256) {
                    float wwv = s_w[pq], ss = 0.f, dr = 0.f;
                    #pragma unroll
                    for (int i = 0; i < 16; i++) {
                        int e = c8 * 16 + i;
                        float er = sigf(s_if[(256 + e) * 2 + pb]);
                        float wv = s_if[(384 + e) * 2 + pb];
                        float m = Mp[i];
                        m = m * (1.0f - wwv * er) + wwv * wv;
                        Mp[i] = m;
                        ss += m * m; dr += m * s_if[e * 2 + pb];
                    }
                    for (int d = 4; d > 0; d >>= 1) {
                        ss += __shfl_down_sync(0xffffffffu, ss, d);
                        dr += __shfl_down_sync(0xffffffffu, dr, d);
                    }
                    if (c8 == 0) { s_mn[pq] = sqrtf(ss); s_md[pq] = dr; }
                }
                BARX();
                // IJ (fused): per-warp wr softmax + r = wr@M, no barrier between
                if (tid < 256) {
                    int b = tid & 1, e = tid >> 1;
                    int lane = tid & 31;
                    int nn = lane >> 1;
                    float br = softplusf(s_if[512*2+b]) + 1.0f;
                    float kn = s_kn[1*2+b];
                    float sc = br * (s_md[b*16+nn] / (s_mn[b*16+nn] * kn + 1e-6f));
                    float mx = sc;
                    #pragma unroll
                    for (int d = 2; d < 32; d <<= 1) mx = fmaxf(mx, __shfl_xor_sync(0xffffffffu, mx, d));
                    float ev = expf(sc - mx);
                    float sum = ev;
                    #pragma unroll
                    for (int d = 2; d < 32; d <<= 1) sum += __shfl_xor_sync(0xffffffffu, sum, d);
                    float wv = ev / sum;
                    const float* Mb = s_M + b * 2048;
                    float r = 0.f;
                    #pragma unroll
                    for (int n = 0; n < 16; n++)
                        r += __shfl_sync(0xffffffffu, wv, n * 2 + b) * Mb[n * 128 + e];
                    s_x[(128 + e) * 2 + b] = r;
                }
            } else {
                // Y: next-step wh partials (h = h2): 96 jq x 4 kq, 32 iters
                int u = tid - 384;
                int jq = u % 96, kq = u / 96;
                u64 a0 = 0, a1 = 0, a2 = 0, a3 = 0;
                const float* wb = p.wh + kq * 32 * 384 + jq * 4;
                const u64* xb = (const u64*)(s_h + kq * 64);
                #pragma unroll
                for (int i = 0; i < 32; i++) {
                    float4 w = __ldg((const float4*)(wb + i * 384));
                    u64 x2 = xb[i];
                    fma2(a0, bc2(w.x), x2); fma2(a1, bc2(w.y), x2);
                    fma2(a2, bc2(w.z), x2); fma2(a3, bc2(w.w), x2);
                }
                u64* d = (u64*)(p_wh + kq * 768 + jq * 8);
                d[0] = a0; d[1] = a1; d[2] = a2; d[3] = a3;
            }
            __syncthreads();
        } else if (s < 399) {
            // serial tail at tile boundary
            if (tid < 256) {
                float ss = 0.f, dw = 0.f;
                #pragma unroll
                for (int i = 0; i < 16; i++) {
                    float m = Mp[i];
                    ss += m * m; dw += m * s_if[(128 + c8 * 16 + i) * 2 + pb];
                }
                for (int d = 4; d > 0; d >>= 1) {
                    ss += __shfl_down_sync(0xffffffffu, ss, d);
                    dw += __shfl_down_sync(0xffffffffu, dw, d);
                }
                if (c8 == 0) { s_mn[pq] = sqrtf(ss); s_md[pq] = dw; }
            } else if (tid < 384) {
                int w = (tid >> 5) - 8, lane = tid & 31;
                int b = w & 1, isr = w >> 1;
                int base = isr ? 0 : 128;
                float t2 = 0.f;
                #pragma unroll
                for (int q = 0; q < 4; q++) {
                    float vq = s_if[(base + lane + q * 32) * 2 + b];
                    t2 += vq * vq;
                }
                for (int d = 16; d > 0; d >>= 1) t2 += __shfl_down_sync(0xffffffffu, t2, d);
                if (lane == 0) s_kn[isr * 2 + b] = sqrtf(t2);
            }
            __syncthreads();
            if (tid < 64 && (tid & 31) < 16) {
                int b = tid >> 5, n = tid & 15;
                float bw = softplusf(s_if[513*2+b]) + 1.0f;
                float gw = sigf(s_if[514*2+b]);
                float kn = s_kn[0*2+b];
                float sc = bw * (s_md[b*16+n] / (s_mn[b*16+n] * kn + 1e-6f));
                float mx = sc;
                for (int d = 8; d > 0; d >>= 1) mx = fmaxf(mx, __shfl_xor_sync(0xffffu, mx, d));
                float e = expf(sc - mx);
                float sum = e;
                for (int d = 8; d > 0; d >>= 1) sum += __shfl_xor_sync(0xffffu, sum, d);
                s_w[b*16+n] = e * (gw / sum);
            }
            __syncthreads();
            if (tid < 256) {
                float wwv = s_w[pq], ss = 0.f, dr = 0.f;
                #pragma unroll
                for (int i = 0; i < 16; i++) {
                    int e = c8 * 16 + i;
                    float er = sigf(s_if[(256 + e) * 2 + pb]);
                    float wv = s_if[(384 + e) * 2 + pb];
                    float m = Mp[i];
                    m = m * (1.0f - wwv * er) + wwv * wv;
                    Mp[i] = m;
                    ss += m * m; dr += m * s_if[e * 2 + pb];
                }
                for (int d = 4; d > 0; d >>= 1) {
                    ss += __shfl_down_sync(0xffffffffu, ss, d);
                    dr += __shfl_down_sync(0xffffffffu, dr, d);
                }
                if (c8 == 0) { s_mn[pq] = sqrtf(ss); s_md[pq] = dr; }
            }
            __syncthreads();
            if (tid < 256) {
                int b = tid & 1, e = tid >> 1;
                int lane = tid & 31;
                int nn = lane >> 1;
                float br = softplusf(s_if[512*2+b]) + 1.0f;
                float kn = s_kn[1*2+b];
                float sc = br * (s_md[b*16+nn] / (s_mn[b*16+nn] * kn + 1e-6f));
                float mx = sc;
                #pragma unroll
                for (int d = 2; d < 32; d <<= 1) mx = fmaxf(mx, __shfl_xor_sync(0xffffffffu, mx, d));
                float ev = expf(sc - mx);
                float sum = ev;
                #pragma unroll
                for (int d = 2; d < 32; d <<= 1) sum += __shfl_xor_sync(0xffffffffu, sum, d);
                float wv = ev / sum;
                const float* Mb = s_M + b * 2048;
                float r = 0.f;
                #pragma unroll
                for (int n = 0; n < 16; n++)
                    r += __shfl_sync(0xffffffffu, wv, n * 2 + b) * Mb[n * 128 + e];
                s_x[(128 + e) * 2 + b] = r;
            }
            __syncthreads();
        }
    }
}

__global__ void __launch_bounds__(768, 1)
fused_kernel(EncP P0, EncP P1, DecP D)
{
    extern __shared__ float sm[];
    int bid = blockIdx.x;
    if (bid < 64) {
        const EncP& p = (bid < 32) ? P0 : P1;
        float* o_out = (bid < 32) ? g_o1 : g_o2;
        enc_body(p, o_out, (bid & 31) * 2, sm);
    } else {
        dec_body(D, bid - 64, sm);
    }
}

// ======= labels + tail copies =======
__global__ void tail_kernel(const int* __restrict__ targets, float* __restrict__ out)
{
    int idx = blockIdx.x * blockDim.x + threadIdx.x;
    if (idx < 25600) {
        int b = idx / 400, ss = idx % 400;
        int t = ss / 25, j = ss % 25;
        float val = (j < 24) ? (float)targets[(b * 16 + t) * 24 + j]
                             : ((t == 15) ? 152.0f : 151.0f);
        out[3916800 + idx] = val;
        if (ss >= 375) out[4187200 + b * 25 + (ss - 375)] = val;
    }
    if (idx < 244800) {
        int b = idx / 3825, rem = idx % 3825;
        out[3942400 + idx] = out[(b * 400 + 375) * 153 + rem];
    }
}

extern "C" void kernel_launch(void* const* d_in, const int* in_sizes, int n_in,
                              void* d_out, int out_size)
{
    (void)in_sizes; (void)n_in; (void)out_size;
    const int*   codes1 = (const int*)d_in[0];
    const int*   codes2 = (const int*)d_in[1];
    const int*   targets= (const int*)d_in[2];

    EncP P0 { codes1, (const float*)d_in[3], (const float*)d_in[6],  (const float*)d_in[7],
              (const float*)d_in[8],  (const float*)d_in[9],
              (const float*)d_in[10], (const float*)d_in[11] };
    EncP P1 { codes2, (const float*)d_in[4], (const float*)d_in[12], (const float*)d_in[13],
              (const float*)d_in[14], (const float*)d_in[15],
              (const float*)d_in[16], (const float*)d_in[17] };
    DecP D  { targets,
              (const float*)d_in[18], (const float*)d_in[19],
              (const float*)d_in[20], (const float*)d_in[21],
              (const float*)d_in[23],
              (const float*)d_in[24], (const float*)d_in[25],
              (const float*)d_in[26], (const float*)d_in[27],
              (const float*)d_in[29],
              (float*)d_out };

    static bool attr_done = false;
    if (!attr_done) {
        cudaFuncSetAttribute(fused_kernel, cudaFuncAttributeMaxDynamicSharedMemorySize, 170000);
        attr_done = true;
    }

    prep_kernel<<<260, 256>>>((const float*)d_in[22], (const float*)d_in[28],
                              (const float*)d_in[5], (const float*)d_in[26]);
    fused_kernel<<<96, 768, 170000>>>(P0, P1, D);
    tail_kernel<<<(244800 + 255) / 256, 256>>>(targets, (float*)d_out);
}

// round 16
// speedup vs baseline: 1.0358x; 1.0358x over previous
#include <cuda_runtime.h>

// MANN_Attn R9 (final): fused pipelined persistent kernel.
//  CTAs 0..31 enc0 (NB=2), 32..63 enc1, 64..95 dec (NB=2), tile-progress flags.
//  Decoder: per-v attention hoisting, token-table comb, FFMA2 float4 GEMVs,
//  smem-cached outw_h + biases (170KB budget), tail overlap (Y: next wh).

typedef unsigned long long u64;

static __device__ float g_o1[16 * 64 * 32 * 64]; // [t][b][l][e]
static __device__ float g_o2[16 * 64 * 32 * 64];
static __device__ __align__(16) float g_wi_pad[128 * 516];
static __device__ __align__(16) float g_outw_pad[256 * 156];
static __device__ __align__(16) float g_tbl[153 * 128];
static __device__ int g_prog[64];

__device__ __forceinline__ float sigf(float x) { return 1.0f / (1.0f + expf(-x)); }
__device__ __forceinline__ float softplusf(float x) { return (x > 15.0f) ? x : log1pf(expf(x)); }
__device__ __forceinline__ u64 bc2(float w) {
    u64 r; asm("mov.b64 %0, {%1, %1};" : "=l"(r) : "f"(w)); return r;
}
__device__ __forceinline__ void fma2(u64& a, u64 w, u64 x) {
    asm("fma.rn.f32x2 %0, %1, %2, %0;" : "+l"(a) : "l"(w), "l"(x));
}
#define BARX() asm volatile("bar.sync 1, 384;" ::: "memory")

__global__ void prep_kernel(const float* __restrict__ wi, const float* __restrict__ outw,
                            const float* __restrict__ emb2, const float* __restrict__ combw)
{
    int i = blockIdx.x * 256 + threadIdx.x;
    if (i < 64) g_prog[i] = 0;
    if (i < 128 * 516) { int k = i / 516, j = i % 516; g_wi_pad[i] = (j < 515) ? wi[k * 515 + j] : 0.f; }
    if (i < 256 * 156) { int k = i / 156, j = i % 156; g_outw_pad[i] = (j < 153) ? outw[k * 153 + j] : 0.f; }
    if (i < 153 * 128) {
        int t = i / 128, j = i % 128;
        float a = 0.f;
        #pragma unroll 8
        for (int e = 0; e < 64; e++) a += emb2[t * 64 + e] * combw[e * 128 + j];
        g_tbl[i] = a;
    }
}

struct EncP {
    const int* codes; const float* emb;
    const float *wx, *wh, *bx, *bh, *wi, *bi;
};
struct DecP {
    const int* targets;
    const float *wx, *wh, *bx, *bh, *bi;
    const float *attn0, *attn1, *combw, *combb, *outb;
    float* out;
};

// ---------------- Encoder body (NB=2, wx from L2) ----------------
__device__ void enc_body(const EncP& p, float* o_out, int b0, float* sm)
{
    const int tid = threadIdx.x;
    float* s_wh = sm;               // 12288 (64x192)
    float* s_wi = s_wh + 12288;     // 16640 (64x260 padded)
    float* s_bx = s_wi + 16640;     // 192
    float* s_bh = s_bx + 192;       // 192
    float* s_bi = s_bh + 192;       // 260
    float* s_p  = s_bi + 260;       // 7680 partial union
    float* s_x  = s_p + 7680;       // 256 [k][b]  (x|r)
    float* s_h  = s_x + 256;        // 128 [j][b]
    float* s_gx = s_h + 128;        // 384
    float* s_gh = s_gx + 384;       // 384
    float* s_if = s_gh + 384;       // 520
    float* s_M  = s_if + 520;       // 2048 [b][n][e]
    float* s_mn = s_M + 2048;       // 32
    float* s_md = s_mn + 32;        // 32
    float* s_w  = s_md + 32;        // 32
    float* s_kn = s_w + 32;         // 8

    float* p_gx = s_p;              // 16 x 384
    float* p_gh = s_p + 6144;       // 4 x 384
    float* p_if = s_p;              // 8 x 520 (reuse)

    for (int i = tid; i < 12288; i += 768) s_wh[i] = p.wh[i];
    for (int i = tid; i < 16640; i += 768) {
        int k = i / 260, j = i % 260;
        s_wi[i] = (j < 259) ? p.wi[k * 259 + j] : 0.f;
    }
    if (tid < 192) { s_bx[tid] = p.bx[tid]; s_bh[tid] = p.bh[tid]; }
    if (tid < 260) s_bi[tid] = (tid < 259) ? p.bi[tid] : 0.f;
    if (tid < 256) s_x[tid] = 0.f;
    if (tid < 128) s_h[tid] = 0.f;
    for (int i = tid; i < 2048; i += 768) s_M[i] = 0.f;
    for (int i = tid; i < 1536; i += 768) p_gh[i] = 0.f;
    __syncthreads();

    const int c8 = tid & 7;
    const int pq = tid >> 3;
    const int pb = pq >> 4;
    float* Mp = s_M + pq * 64 + c8 * 8;

    if (tid < 128) {
        int b = tid & 1, e = tid >> 1;
        int code = p.codes[(b0 + b) * 512 + 0];
        s_x[e * 2 + b] = p.emb[code * 64 + e];
    }
    __syncthreads();

    for (int s = 0; s < 512; ++s) {
        // B: gx partials (wx from L2): 48 jq x 16 kq = 768 threads, 8 iters
        {
            int jq = tid % 48, kq = tid / 48;
            u64 a0 = 0, a1 = 0, a2 = 0, a3 = 0;
            const float* wb = p.wx + kq * 8 * 192 + jq * 4;
            const u64* xb = (const u64*)(s_x + kq * 16);
            #pragma unroll
            for (int i = 0; i < 8; i++) {
                float4 w = __ldg((const float4*)(wb + i * 192));
                u64 x2 = xb[i];
                fma2(a0, bc2(w.x), x2); fma2(a1, bc2(w.y), x2);
                fma2(a2, bc2(w.z), x2); fma2(a3, bc2(w.w), x2);
            }
            u64* d = (u64*)(p_gx + kq * 384 + jq * 8);
            d[0] = a0; d[1] = a1; d[2] = a2; d[3] = a3;
        }
        __syncthreads();
        // C: reduce gx (384) + gh (384)
        if (tid < 384) {
            float a = s_bx[tid >> 1];
            #pragma unroll
            for (int kq = 0; kq < 16; kq++) a += p_gx[kq * 384 + tid];
            s_gx[tid] = a;
        } else {
            int u = tid - 384;
            float g = s_bh[u >> 1];
            #pragma unroll
            for (int kh = 0; kh < 4; kh++) g += p_gh[kh * 384 + u];
            s_gh[u] = g;
        }
        __syncthreads();
        // GRU
        if (tid < 128) {
            int b = tid & 1, j = tid >> 1;
            float xr = s_gx[j*2+b], xz = s_gx[(64+j)*2+b], xn = s_gx[(128+j)*2+b];
            float hr = s_gh[j*2+b], hz = s_gh[(64+j)*2+b], hn = s_gh[(128+j)*2+b];
            float rg = sigf(xr + hr), z = sigf(xz + hz);
            float n = tanhf(xn + rg * hn);
            s_h[j*2+b] = (1.0f - z) * n + z * s_h[j*2+b];
        }
        __syncthreads();
        // iface partials: 65 jq x 8 kq = 520 threads, 8 iters
        if (tid < 520) {
            int jq = tid % 65, kq = tid / 65;
            u64 a0 = 0, a1 = 0, a2 = 0, a3 = 0;
            const float* wb = s_wi + kq * 8 * 260 + jq * 4;
            const u64* xb = (const u64*)(s_h + kq * 16);
            #pragma unroll
            for (int i = 0; i < 8; i++) {
                float4 w = *(const float4*)(wb + i * 260);
                u64 x2 = xb[i];
                fma2(a0, bc2(w.x), x2); fma2(a1, bc2(w.y), x2);
                fma2(a2, bc2(w.z), x2); fma2(a3, bc2(w.w), x2);
            }
            u64* d = (u64*)(p_if + kq * 520 + jq * 8);
            d[0] = a0; d[1] = a1; d[2] = a2; d[3] = a3;
        }
        __syncthreads();
        if (tid < 520) {
            float a = s_bi[tid >> 1];
            #pragma unroll
            for (int kq = 0; kq < 8; kq++) a += p_if[kq * 520 + tid];
            s_if[tid] = a;
        }
        __syncthreads();

        if (s < 511) {
            if (tid < 384) {
                if (tid < 256) {
                    float ss = 0.f, dw = 0.f;
                    #pragma unroll
                    for (int i = 0; i < 8; i++) {
                        float m = Mp[i];
                        ss += m * m; dw += m * s_if[(64 + c8 * 8 + i) * 2 + pb];
                    }
                    for (int d = 4; d > 0; d >>= 1) {
                        ss += __shfl_down_sync(0xffffffffu, ss, d);
                        dw += __shfl_down_sync(0xffffffffu, dw, d);
                    }
                    if (c8 == 0) { s_mn[pq] = sqrtf(ss); s_md[pq] = dw; }
                } else {
                    int w = (tid >> 5) - 8, lane = tid & 31;
                    int b = w & 1, isr = w >> 1;
                    int base = isr ? 0 : 64;
                    float v0 = s_if[(base + lane) * 2 + b], v1 = s_if[(base + 32 + lane) * 2 + b];
                    float t2 = v0 * v0 + v1 * v1;
                    for (int d = 16; d > 0; d >>= 1) t2 += __shfl_down_sync(0xffffffffu, t2, d);
                    if (lane == 0) s_kn[isr * 2 + b] = sqrtf(t2);
                }
                BARX();
                if (tid < 64 && (tid & 31) < 16) {
                    int b = tid >> 5, n = tid & 15;
                    float bw = softplusf(s_if[257*2+b]) + 1.0f;
                    float gw = sigf(s_if[258*2+b]);
                    float kn = s_kn[0*2+b];
                    float sc = bw * (s_md[b*16+n] / (s_mn[b*16+n] * kn + 1e-6f));
                    float mx = sc;
                    for (int d = 8; d > 0; d >>= 1) mx = fmaxf(mx, __shfl_xor_sync(0xffffu, mx, d));
                    float e = expf(sc - mx);
                    float sum = e;
                    for (int d = 8; d > 0; d >>= 1) sum += __shfl_xor_sync(0xffffu, sum, d);
                    s_w[b*16+n] = e * (gw / sum);
                }
                BARX();
                if (tid < 256) {
                    float wwv = s_w[pq], ss = 0.f, dr = 0.f;
                    #pragma unroll
                    for (int i = 0; i < 8; i++) {
                        int e = c8 * 8 + i;
                        float er = sigf(s_if[(128 + e) * 2 + pb]);
                        float wv = s_if[(192 + e) * 2 + pb];
                        float m = Mp[i];
                        m = m * (1.0f - wwv * er) + wwv * wv;
                        Mp[i] = m;
                        ss += m * m; dr += m * s_if[e * 2 + pb];
                    }
                    for (int d = 4; d > 0; d >>= 1) {
                        ss += __shfl_down_sync(0xffffffffu, ss, d);
                        dr += __shfl_down_sync(0xffffffffu, dr, d);
                    }
                    if (c8 == 0) { s_mn[pq] = sqrtf(ss); s_md[pq] = dr; }
                }
                BARX();
                if (tid < 64 && (tid & 31) < 16) {
                    int b = tid >> 5, n = tid & 15;
                    float br = softplusf(s_if[256*2+b]) + 1.0f;
                    float kn = s_kn[1*2+b];
                    float sc = br * (s_md[b*16+n] / (s_mn[b*16+n] * kn + 1e-6f));
                    float mx = sc;
                    for (int d = 8; d > 0; d >>= 1) mx = fmaxf(mx, __shfl_xor_sync(0xffffu, mx, d));
                    float e = expf(sc - mx);
                    float sum = e;
                    for (int d = 8; d > 0; d >>= 1) sum += __shfl_xor_sync(0xffffu, sum, d);
                    s_w[b*16+n] = e / sum;
                }
                BARX();
                if (tid < 128) {
                    int b = tid & 1, e = tid >> 1;
                    const float* Mb = s_M + b * 1024;
                    float r = 0.f;
                    #pragma unroll
                    for (int n = 0; n < 16; n++) r += s_w[b*16+n] * Mb[n * 64 + e];
                    s_x[(64 + e) * 2 + b] = r;
                    o_out[(((s >> 5) * 64 + (b0 + b)) * 32 + (s & 31)) * 64 + e] = s_h[e * 2 + b];
                }
            } else if (tid < 576) {
                int u = tid - 384;
                int jq = u % 48, kh = u / 48;
                u64 a0 = 0, a1 = 0, a2 = 0, a3 = 0;
                const float* wb = s_wh + kh * 16 * 192 + jq * 4;
                const u64* xb = (const u64*)(s_h + kh * 32);
                #pragma unroll
                for (int i = 0; i < 16; i++) {
                    float4 w = *(const float4*)(wb + i * 192);
                    u64 x2 = xb[i];
                    fma2(a0, bc2(w.x), x2); fma2(a1, bc2(w.y), x2);
                    fma2(a2, bc2(w.z), x2); fma2(a3, bc2(w.w), x2);
                }
                u64* d = (u64*)(p_gh + kh * 384 + jq * 8);
                d[0] = a0; d[1] = a1; d[2] = a2; d[3] = a3;
            } else if (tid < 704) {
                int u = tid - 576;
                int b = u & 1, e = u >> 1;
                int code = p.codes[(b0 + b) * 512 + (s + 1)];
                s_x[e * 2 + b] = p.emb[code * 64 + e];
            }
            __syncthreads();
        } else {
            if (tid < 128) {
                int b = tid & 1, e = tid >> 1;
                o_out[(((s >> 5) * 64 + (b0 + b)) * 32 + (s & 31)) * 64 + e] = s_h[e * 2 + b];
            }
            __syncthreads();
        }
        if ((s & 31) == 31) {
            __threadfence();
            if (tid == 0) atomicExch(&g_prog[blockIdx.x], (s >> 5) + 1);
        }
    }
}

// ---------------- Decoder body (NB=2, smem outw_h/bias caches) ----------------
__device__ void dec_body(const DecP& p, int jj, float* sm)
{
    const int b0 = jj * 2;
    const int tid = threadIdx.x;

    float* s_ow = sm;            // 19968 (128x156) outw h-half cache
    float* s_p  = s_ow + 19968;  // 12288 partial union
    float* s_x  = s_p + 12288;   // 512
    float* s_h  = s_x + 512;     // 256
    float* s_gx = s_h + 256;     // 768
    float* s_gh = s_gx + 768;    // 768
    float* s_if = s_gh + 768;    // 1032
    float* s_M  = s_if + 1032;   // 4096
    float* s_c  = s_M + 4096;    // 256
    float* s_cc = s_c + 256;     // 256
    float* s_oc = s_cc + 256;    // 312
    float* s_at = s_oc + 312;    // 128
    float* s_mn = s_at + 128;    // 32
    float* s_md = s_mn + 32;     // 32
    float* s_w  = s_md + 32;     // 32
    float* s_kn = s_w + 32;      // 8
    float* s_bx2 = s_kn + 8;     // 384
    float* s_bh2 = s_bx2 + 384;  // 384
    float* s_bi2 = s_bh2 + 384;  // 520

    float* p_wx = s_p;           // 8 x 768
    float* p_wh = s_p + 6144;    // 4 x 768
    float* p_if = s_p;           // 4 x 1032
    float* p_oh = s_p + 4224;    // 4 x 312
    float* p_cb = s_p;           // 4 x 256 (per-v)
    float* p_oc = s_p + 1024;    // 4 x 312 (per-v)

    for (int i = tid; i < 19968; i += 768) s_ow[i] = g_outw_pad[i];
    for (int i = tid; i < 512; i += 768) s_x[i] = 0.f;
    for (int i = tid; i < 4096; i += 768) s_M[i] = 0.f;
    if (tid < 384) { s_bx2[tid] = p.bx[tid]; s_bh2[tid] = p.bh[tid]; }
    if (tid < 520) s_bi2[tid] = (tid < 515) ? p.bi[tid] : 0.f;
    __syncthreads();

    if (tid == 0) {
        while (*(volatile int*)&g_prog[jj] < 1 || *(volatile int*)&g_prog[32 + jj] < 1)
            __nanosleep(200);
    }
    __syncthreads();
    if (tid < 256) {
        int b = tid & 1, e = tid >> 1;
        float h = (e < 64) ? g_o1[((b0 + b) * 32 + 31) * 64 + e]
                           : g_o2[((b0 + b) * 32 + 31) * 64 + (e - 64)];
        s_h[e * 2 + b] = h;
    }
    __syncthreads();

    const int c8 = tid & 7;
    const int pq = tid >> 3;
    const int pb = pq >> 4;
    float* Mp = s_M + pq * 128 + c8 * 16;

    for (int s = 0; s < 400; ++s) {
        const int v = s / 25, pos = s - v * 25;

        if (pos == 0) {
            if (tid == 0) {
                while (*(volatile int*)&g_prog[jj] <= v || *(volatile int*)&g_prog[32 + jj] <= v)
                    __nanosleep(200);
            }
            __syncthreads();
            // V0: attention scores
            if (tid < 256) {
                int cc = tid & 1, g = tid >> 1;
                int a = g >> 6, b = (g >> 5) & 1, l = g & 31;
                const float* op = (a ? g_o2 : g_o1) + ((v * 64 + (b0 + b)) * 32 + l) * 64 + cc * 32;
                const float* aw = (a ? p.attn1 : p.attn0) + 128 + cc * 32;
                float sc = 0.f;
                #pragma unroll
                for (int e = 0; e < 32; e++) sc += op[e] * __ldg(aw + e);
                sc += __shfl_down_sync(0xffffffffu, sc, 1);
                if (cc == 0) s_at[g] = sc;
            }
            __syncthreads();
            // V1: softmax
            if (tid < 128) {
                int w = tid >> 5, l = tid & 31;
                float vsc = s_at[w * 32 + l];
                float mx = vsc;
                for (int d = 16; d > 0; d >>= 1) mx = fmaxf(mx, __shfl_xor_sync(0xffffffffu, mx, d));
                float e2 = expf(vsc - mx);
                float sum = e2;
                for (int d = 16; d > 0; d >>= 1) sum += __shfl_xor_sync(0xffffffffu, sum, d);
                s_at[w * 32 + l] = e2 / sum;
            }
            __syncthreads();
            // V2: contexts
            if (tid < 256) {
                int a = tid >> 7, b = (tid >> 6) & 1, e = tid & 63;
                const float* op = (a ? g_o2 : g_o1) + ((v * 64 + (b0 + b)) * 32) * 64 + e;
                const float* at = s_at + a * 64 + b * 32;
                float cv = 0.f;
                #pragma unroll
                for (int l = 0; l < 32; l++) cv += at[l] * op[l * 64];
                s_c[(a * 64 + e) * 2 + b] = cv;
            }
            __syncthreads();
            // V3: comb_cc + out_cc partials
            if (tid < 128) {
                int jq = tid & 31, kq = tid >> 5;
                u64 a0 = 0, a1 = 0, a2 = 0, a3 = 0;
                const float* wb = p.combw + (64 + kq * 32) * 128 + jq * 4;
                const u64* xb = (const u64*)(s_c + kq * 64);
                #pragma unroll
                for (int i = 0; i < 32; i++) {
                    float4 w = __ldg((const float4*)(wb + i * 128));
                    u64 x2 = xb[i];
                    fma2(a0, bc2(w.x), x2); fma2(a1, bc2(w.y), x2);
                    fma2(a2, bc2(w.z), x2); fma2(a3, bc2(w.w), x2);
                }
                u64* d = (u64*)(p_cb + kq * 256 + jq * 8);
                d[0] = a0; d[1] = a1; d[2] = a2; d[3] = a3;
            } else if (tid < 284) {
                int u = tid - 128;
                int jq = u % 39, kq = u / 39;
                u64 a0 = 0, a1 = 0, a2 = 0, a3 = 0;
                const float* wb = g_outw_pad + (128 + kq * 32) * 156 + jq * 4;
                const u64* xb = (const u64*)(s_c + kq * 64);
                #pragma unroll
                for (int i = 0; i < 32; i++) {
                    float4 w = *(const float4*)(wb + i * 156);
                    u64 x2 = xb[i];
                    fma2(a0, bc2(w.x), x2); fma2(a1, bc2(w.y), x2);
                    fma2(a2, bc2(w.z), x2); fma2(a3, bc2(w.w), x2);
                }
                u64* d = (u64*)(p_oc + kq * 312 + jq * 8);
                d[0] = a0; d[1] = a1; d[2] = a2; d[3] = a3;
            }
            __syncthreads();
            // V4: reduce
            if (tid < 256) {
                float a = __ldg(p.combb + (tid >> 1));
                #pragma unroll
                for (int kq = 0; kq < 4; kq++) a += p_cb[kq * 256 + tid];
                s_cc[tid] = a;
            } else if (tid < 568) {
                int idx = tid - 256;
                int j = idx >> 1;
                float a = (j < 153) ? __ldg(p.outb + j) : 0.f;
                #pragma unroll
                for (int kq = 0; kq < 4; kq++) a += p_oc[kq * 312 + idx];
                s_oc[idx] = a;
            }
            __syncthreads();
            // A-inline: comb (start/split token) + wh partials
            if (tid < 256) {
                int tok = (v == 0) ? 150 : 151;
                s_x[tid] = fmaxf(__ldg(g_tbl + tok * 128 + (tid >> 1)) + s_cc[tid], 0.f);
            } else if (tid < 640) {
                int u = tid - 256;
                int jq = u % 96, kq = u / 96;
                u64 a0 = 0, a1 = 0, a2 = 0, a3 = 0;
                const float* wb = p.wh + kq * 32 * 384 + jq * 4;
                const u64* xb = (const u64*)(s_h + kq * 64);
                #pragma unroll
                for (int i = 0; i < 32; i++) {
                    float4 w = __ldg((const float4*)(wb + i * 384));
                    u64 x2 = xb[i];
                    fma2(a0, bc2(w.x), x2); fma2(a1, bc2(w.y), x2);
                    fma2(a2, bc2(w.z), x2); fma2(a3, bc2(w.w), x2);
                }
                u64* d = (u64*)(p_wh + kq * 768 + jq * 8);
                d[0] = a0; d[1] = a1; d[2] = a2; d[3] = a3;
            }
            __syncthreads();
        }

        // B: wx partials: 96 jq x 8 kq = 768 threads, 32 iters
        {
            int jq = tid % 96, kq = tid / 96;
            u64 a0 = 0, a1 = 0, a2 = 0, a3 = 0;
            const float* wb = p.wx + kq * 32 * 384 + jq * 4;
            const u64* xb = (const u64*)(s_x + kq * 64);
            #pragma unroll
            for (int i = 0; i < 32; i++) {
                float4 w = __ldg((const float4*)(wb + i * 384));
                u64 x2 = xb[i];
                fma2(a0, bc2(w.x), x2); fma2(a1, bc2(w.y), x2);
                fma2(a2, bc2(w.z), x2); fma2(a3, bc2(w.w), x2);
            }
            u64* d = (u64*)(p_wx + kq * 768 + jq * 8);
            d[0] = a0; d[1] = a1; d[2] = a2; d[3] = a3;
        }
        __syncthreads();
        // C1: reduce gx/gh
        {
            float a = s_bx2[tid >> 1];
            float g = s_bh2[tid >> 1];
            #pragma unroll
            for (int kq = 0; kq < 8; kq++) a += p_wx[kq * 768 + tid];
            #pragma unroll
            for (int kq = 0; kq < 4; kq++) g += p_wh[kq * 768 + tid];
            s_gx[tid] = a; s_gh[tid] = g;
        }
        __syncthreads();
        // C2: GRU
        if (tid < 256) {
            int b = tid & 1, j = tid >> 1;
            float xr = s_gx[j*2+b], xz = s_gx[(128+j)*2+b], xn = s_gx[(256+j)*2+b];
            float hr = s_gh[j*2+b], hz = s_gh[(128+j)*2+b], hn = s_gh[(256+j)*2+b];
            float rg = sigf(xr + hr), z = sigf(xz + hz);
            float n = tanhf(xn + rg * hn);
            s_h[j*2+b] = (1.0f - z) * n + z * s_h[j*2+b];
        }
        __syncthreads();
        // D: wi (L2) + outw_h (smem) partials
        if (tid < 516) {
            int jq = tid % 129, kq = tid / 129;
            u64 a0 = 0, a1 = 0, a2 = 0, a3 = 0;
            const float* wb = g_wi_pad + kq * 32 * 516 + jq * 4;
            const u64* xb = (const u64*)(s_h + kq * 64);
            #pragma unroll
            for (int i = 0; i < 32; i++) {
                float4 w = *(const float4*)(wb + i * 516);
                u64 x2 = xb[i];
                fma2(a0, bc2(w.x), x2); fma2(a1, bc2(w.y), x2);
                fma2(a2, bc2(w.z), x2); fma2(a3, bc2(w.w), x2);
            }
            u64* d = (u64*)(p_if + kq * 1032 + jq * 8);
            d[0] = a0; d[1] = a1; d[2] = a2; d[3] = a3;
        } else if (tid < 672) {
            int u = tid - 516;
            int jq = u % 39, kq = u / 39;
            u64 a0 = 0, a1 = 0, a2 = 0, a3 = 0;
            const float* wb = s_ow + kq * 32 * 156 + jq * 4;
            const u64* xb = (const u64*)(s_h + kq * 64);
            #pragma unroll
            for (int i = 0; i < 32; i++) {
                float4 w = *(const float4*)(wb + i * 156);
                u64 x2 = xb[i];
                fma2(a0, bc2(w.x), x2); fma2(a1, bc2(w.y), x2);
                fma2(a2, bc2(w.z), x2); fma2(a3, bc2(w.w), x2);
            }
            u64* d = (u64*)(p_oh + kq * 312 + jq * 8);
            d[0] = a0; d[1] = a1; d[2] = a2; d[3] = a3;
        }
        __syncthreads();
        // E: reduce iface + logits store
        for (int u = tid; u < 1030; u += 768) {
            float a = s_bi2[u >> 1];
            #pragma unroll
            for (int kq = 0; kq < 4; kq++) a += p_if[kq * 1032 + u];
            s_if[u] = a;
        }
        if (tid < 306) {
            int j = tid >> 1, b = tid & 1;
            float a = s_oc[tid];
            #pragma unroll
            for (int kq = 0; kq < 4; kq++) a += p_oh[kq * 312 + tid];
            p.out[((b0 + b) * 400 + s) * 153 + j] = a;
        }
        __syncthreads();

        if (pos < 24) {
            if (tid < 384) {
                if (tid < 256) {
                    float ss = 0.f, dw = 0.f;
                    #pragma unroll
                    for (int i = 0; i < 16; i++) {
                        float m = Mp[i];
                        ss += m * m; dw += m * s_if[(128 + c8 * 16 + i) * 2 + pb];
                    }
                    for (int d = 4; d > 0; d >>= 1) {
                        ss += __shfl_down_sync(0xffffffffu, ss, d);
                        dw += __shfl_down_sync(0xffffffffu, dw, d);
                    }
                    if (c8 == 0) { s_mn[pq] = sqrtf(ss); s_md[pq] = dw; }
                } else {
                    int w = (tid >> 5) - 8, lane = tid & 31;
                    int b = w & 1, isr = w >> 1;
                    int base = isr ? 0 : 128;
                    float t2 = 0.f;
                    #pragma unroll
                    for (int q = 0; q < 4; q++) {
                        float vq = s_if[(base + lane + q * 32) * 2 + b];
                        t2 += vq * vq;
                    }
                    for (int d = 16; d > 0; d >>= 1) t2 += __shfl_down_sync(0xffffffffu, t2, d);
                    if (lane == 0) s_kn[isr * 2 + b] = sqrtf(t2);
                }
                BARX();
                if (tid < 64) {
                    if ((tid & 31) < 16) {
                        int b = tid >> 5, n = tid & 15;
                        float bw = softplusf(s_if[513*2+b]) + 1.0f;
                        float gw = sigf(s_if[514*2+b]);
                        float kn = s_kn[0*2+b];
                        float sc = bw * (s_md[b*16+n] / (s_mn[b*16+n] * kn + 1e-6f));
                        float mx = sc;
                        for (int d = 8; d > 0; d >>= 1) mx = fmaxf(mx, __shfl_xor_sync(0xffffu, mx, d));
                        float e = expf(sc - mx);
                        float sum = e;
                        for (int d = 8; d > 0; d >>= 1) sum += __shfl_xor_sync(0xffffu, sum, d);
                        s_w[b*16+n] = e * (gw / sum);
                    }
                } else if (tid < 320) {
                    int idx = tid - 64;
                    int b = idx & 1, j = idx >> 1;
                    int tok = p.targets[((b0 + b) * 16 + v) * 24 + pos];
                    s_x[idx] = fmaxf(__ldg(g_tbl + tok * 128 + j) + s_cc[idx], 0.f);
                }
                BARX();
                if (tid < 256) {
                    float wwv = s_w[pq], ss = 0.f, dr = 0.f;
                    #pragma unroll
                    for (int i = 0; i < 16; i++) {
                        int e = c8 * 16 + i;
                        float er = sigf(s_if[(256 + e) * 2 + pb]);
                        float wv = s_if[(384 + e) * 2 + pb];
                        float m = Mp[i];
                        m = m * (1.0f - wwv * er) + wwv * wv;
                        Mp[i] = m;
                        ss += m * m; dr += m * s_if[e * 2 + pb];
                    }
                    for (int d = 4; d > 0; d >>= 1) {
                        ss += __shfl_down_sync(0xffffffffu, ss, d);
                        dr += __shfl_down_sync(0xffffffffu, dr, d);
                    }
                    if (c8 == 0) { s_mn[pq] = sqrtf(ss); s_md[pq] = dr; }
                }
                BARX();
                if (tid < 64 && (tid & 31) < 16) {
                    int b = tid >> 5, n = tid & 15;
                    float br = softplusf(s_if[512*2+b]) + 1.0f;
                    float kn = s_kn[1*2+b];
                    float sc = br * (s_md[b*16+n] / (s_mn[b*16+n] * kn + 1e-6f));
                    float mx = sc;
                    for (int d = 8; d > 0; d >>= 1) mx = fmaxf(mx, __shfl_xor_sync(0xffffu, mx, d));
                    float e = expf(sc - mx);
                    float sum = e;
                    for (int d = 8; d > 0; d >>= 1) sum += __shfl_xor_sync(0xffffu, sum, d);
                    s_w[b*16+n] = e / sum;
                }
                BARX();
                if (tid < 256) {
                    int b = tid & 1, e = tid >> 1;
                    const float* Mb = s_M + b * 2048;
                    float r = 0.f;
                    #pragma unroll
                    for (int n = 0; n < 16; n++) r += s_w[b*16+n] * Mb[n * 128 + e];
                    s_x[(128 + e) * 2 + b] = r;
                }
            } else {
                // Y: next-step wh partials (h = h2): 96 jq x 4 kq, 32 iters
                int u = tid - 384;
                int jq = u % 96, kq = u / 96;
                u64 a0 = 0, a1 = 0, a2 = 0, a3 = 0;
                const float* wb = p.wh + kq * 32 * 384 + jq * 4;
                const u64* xb = (const u64*)(s_h + kq * 64);
                #pragma unroll
                for (int i = 0; i < 32; i++) {
                    float4 w = __ldg((const float4*)(wb + i * 384));
                    u64 x2 = xb[i];
                    fma2(a0, bc2(w.x), x2); fma2(a1, bc2(w.y), x2);
                    fma2(a2, bc2(w.z), x2); fma2(a3, bc2(w.w), x2);
                }
                u64* d = (u64*)(p_wh + kq * 768 + jq * 8);
                d[0] = a0; d[1] = a1; d[2] = a2; d[3] = a3;
            }
            __syncthreads();
        } else if (s < 399) {
            // serial tail at tile boundary
            if (tid < 256) {
                float ss = 0.f, dw = 0.f;
                #pragma unroll
                for (int i = 0; i < 16; i++) {
                    float m = Mp[i];
                    ss += m * m; dw += m * s_if[(128 + c8 * 16 + i) * 2 + pb];
                }
                for (int d = 4; d > 0; d >>= 1) {
                    ss += __shfl_down_sync(0xffffffffu, ss, d);
                    dw += __shfl_down_sync(0xffffffffu, dw, d);
                }
                if (c8 == 0) { s_mn[pq] = sqrtf(ss); s_md[pq] = dw; }
            } else if (tid < 384) {
                int w = (tid >> 5) - 8, lane = tid & 31;
                int b = w & 1, isr = w >> 1;
                int base = isr ? 0 : 128;
                float t2 = 0.f;
                #pragma unroll
                for (int q = 0; q < 4; q++) {
                    float vq = s_if[(base + lane + q * 32) * 2 + b];
                    t2 += vq * vq;
                }
                for (int d = 16; d > 0; d >>= 1) t2 += __shfl_down_sync(0xffffffffu, t2, d);
                if (lane == 0) s_kn[isr * 2 + b] = sqrtf(t2);
            }
            __syncthreads();
            if (tid < 64 && (tid & 31) < 16) {
                int b = tid >> 5, n = tid & 15;
                float bw = softplusf(s_if[513*2+b]) + 1.0f;
                float gw = sigf(s_if[514*2+b]);
                float kn = s_kn[0*2+b];
                float sc = bw * (s_md[b*16+n] / (s_mn[b*16+n] * kn + 1e-6f));
                float mx = sc;
                for (int d = 8; d > 0; d >>= 1) mx = fmaxf(mx, __shfl_xor_sync(0xffffu, mx, d));
                float e = expf(sc - mx);
                float sum = e;
                for (int d = 8; d > 0; d >>= 1) sum += __shfl_xor_sync(0xffffu, sum, d);
                s_w[b*16+n] = e * (gw / sum);
            }
            __syncthreads();
            if (tid < 256) {
                float wwv = s_w[pq], ss = 0.f, dr = 0.f;
                #pragma unroll
                for (int i = 0; i < 16; i++) {
                    int e = c8 * 16 + i;
                    float er = sigf(s_if[(256 + e) * 2 + pb]);
                    float wv = s_if[(384 + e) * 2 + pb];
                    float m = Mp[i];
                    m = m * (1.0f - wwv * er) + wwv * wv;
                    Mp[i] = m;
                    ss += m * m; dr += m * s_if[e * 2 + pb];
                }
                for (int d = 4; d > 0; d >>= 1) {
                    ss += __shfl_down_sync(0xffffffffu, ss, d);
                    dr += __shfl_down_sync(0xffffffffu, dr, d);
                }
                if (c8 == 0) { s_mn[pq] = sqrtf(ss); s_md[pq] = dr; }
            }
            __syncthreads();
            if (tid < 64 && (tid & 31) < 16) {
                int b = tid >> 5, n = tid & 15;
                float br = softplusf(s_if[512*2+b]) + 1.0f;
                float kn = s_kn[1*2+b];
                float sc = br * (s_md[b*16+n] / (s_mn[b*16+n] * kn + 1e-6f));
                float mx = sc;
                for (int d = 8; d > 0; d >>= 1) mx = fmaxf(mx, __shfl_xor_sync(0xffffu, mx, d));
                float e = expf(sc - mx);
                float sum = e;
                for (int d = 8; d > 0; d >>= 1) sum += __shfl_xor_sync(0xffffu, sum, d);
                s_w[b*16+n] = e / sum;
            }
            __syncthreads();
            if (tid < 256) {
                int b = tid & 1, e = tid >> 1;
                const float* Mb = s_M + b * 2048;
                float r = 0.f;
                #pragma unroll
                for (int n = 0; n < 16; n++) r += s_w[b*16+n] * Mb[n * 128 + e];
                s_x[(128 + e) * 2 + b] = r;
            }
            __syncthreads();
        }
    }
}

__global__ void __launch_bounds__(768, 1)
fused_kernel(EncP P0, EncP P1, DecP D)
{
    extern __shared__ float sm[];
    int bid = blockIdx.x;
    if (bid < 64) {
        const EncP& p = (bid < 32) ? P0 : P1;
        float* o_out = (bid < 32) ? g_o1 : g_o2;
        enc_body(p, o_out, (bid & 31) * 2, sm);
    } else {
        dec_body(D, bid - 64, sm);
    }
}

// ======= labels + tail copies =======
__global__ void tail_kernel(const int* __restrict__ targets, float* __restrict__ out)
{
    int idx = blockIdx.x * blockDim.x + threadIdx.x;
    if (idx < 25600) {
        int b = idx / 400, ss = idx % 400;
        int t = ss / 25, j = ss % 25;
        float val = (j < 24) ? (float)targets[(b * 16 + t) * 24 + j]
                             : ((t == 15) ? 152.0f : 151.0f);
        out[3916800 + idx] = val;
        if (ss >= 375) out[4187200 + b * 25 + (ss - 375)] = val;
    }
    if (idx < 244800) {
        int b = idx / 3825, rem = idx % 3825;
        out[3942400 + idx] = out[(b * 400 + 375) * 153 + rem];
    }
}

extern "C" void kernel_launch(void* const* d_in, const int* in_sizes, int n_in,
                              void* d_out, int out_size)
{
    (void)in_sizes; (void)n_in; (void)out_size;
    const int*   codes1 = (const int*)d_in[0];
    const int*   codes2 = (const int*)d_in[1];
    const int*   targets= (const int*)d_in[2];

    EncP P0 { codes1, (const float*)d_in[3], (const float*)d_in[6],  (const float*)d_in[7],
              (const float*)d_in[8],  (const float*)d_in[9],
              (const float*)d_in[10], (const float*)d_in[11] };
    EncP P1 { codes2, (const float*)d_in[4], (const float*)d_in[12], (const float*)d_in[13],
              (const float*)d_in[14], (const float*)d_in[15],
              (const float*)d_in[16], (const float*)d_in[17] };
    DecP D  { targets,
              (const float*)d_in[18], (const float*)d_in[19],
              (const float*)d_in[20], (const float*)d_in[21],
              (const float*)d_in[23],
              (const float*)d_in[24], (const float*)d_in[25],
              (const float*)d_in[26], (const float*)d_in[27],
              (const float*)d_in[29],
              (float*)d_out };

    static bool attr_done = false;
    if (!attr_done) {
        cudaFuncSetAttribute(fused_kernel, cudaFuncAttributeMaxDynamicSharedMemorySize, 170000);
        attr_done = true;
    }

    prep_kernel<<<260, 256>>>((const float*)d_in[22], (const float*)d_in[28],
                              (const float*)d_in[5], (const float*)d_in[26]);
    fused_kernel<<<96, 768, 170000>>>(P0, P1, D);
    tail_kernel<<<(244800 + 255) / 256, 256>>>(targets, (float*)d_out);
}

// round 17
// speedup vs baseline: 1.0637x; 1.0270x over previous
#include <cuda_runtime.h>
#include <cuda_fp16.h>

// MANN_Attn R16: R9 + fp16 storage for dec wh/wi streams (8-j span, half the
// LDG count in D and tail-Y phases). Math stays fp32 FFMA2. Enc unchanged.
//  CTAs 0..31 enc0 (NB=2), 32..63 enc1, 64..95 dec (NB=2), pipelined flags.

typedef unsigned long long u64;

static __device__ float g_o1[16 * 64 * 32 * 64]; // [t][b][l][e]
static __device__ float g_o2[16 * 64 * 32 * 64];
static __device__ __align__(16) float g_wi_pad[128 * 516];   // (legacy, unused by dec now)
static __device__ __align__(16) float g_outw_pad[256 * 156];
static __device__ __align__(16) float g_tbl[153 * 128];
static __device__ __align__(16) __half g_wh_h[128 * 384];    // dec wh fp16
static __device__ __align__(16) __half g_wi_h[128 * 520];    // dec wi fp16 (row 520)
static __device__ int g_prog[64];

__device__ __forceinline__ float sigf(float x) { return 1.0f / (1.0f + expf(-x)); }
__device__ __forceinline__ float softplusf(float x) { return (x > 15.0f) ? x : log1pf(expf(x)); }
__device__ __forceinline__ u64 bc2(float w) {
    u64 r; asm("mov.b64 %0, {%1, %1};" : "=l"(r) : "f"(w)); return r;
}
__device__ __forceinline__ void fma2(u64& a, u64 w, u64 x) {
    asm("fma.rn.f32x2 %0, %1, %2, %0;" : "+l"(a) : "l"(w), "l"(x));
}
#define BARX() asm volatile("bar.sync 1, 384;" ::: "memory")

// 8-j fp16-weight GEMV partial: thread owns 8 adjacent j for both b.
template<int IT, int ROW>
__device__ __forceinline__ void gemv_h8(const __half* wb, const float* xb0, float* dst)
{
    u64 A[8] = {0, 0, 0, 0, 0, 0, 0, 0};
    const u64* xb = (const u64*)xb0;
    #pragma unroll
    for (int i = 0; i < IT; i++) {
        uint4 wv = *(const uint4*)(wb + i * ROW);
        u64 x2 = xb[i];
        const __half2* h = (const __half2*)&wv;
        #pragma unroll
        for (int q = 0; q < 4; q++) {
            float2 f = __half22float2(h[q]);
            fma2(A[2 * q],     bc2(f.x), x2);
            fma2(A[2 * q + 1], bc2(f.y), x2);
        }
    }
    u64* d = (u64*)dst;
    #pragma unroll
    for (int q = 0; q < 8; q++) d[q] = A[q];
}

__global__ void prep_kernel(const float* __restrict__ wi, const float* __restrict__ outw,
                            const float* __restrict__ emb2, const float* __restrict__ combw,
                            const float* __restrict__ wh)
{
    int i = blockIdx.x * 256 + threadIdx.x;
    if (i < 64) g_prog[i] = 0;
    if (i < 128 * 516) { int k = i / 516, j = i % 516; g_wi_pad[i] = (j < 515) ? wi[k * 515 + j] : 0.f; }
    if (i < 256 * 156) { int k = i / 156, j = i % 156; g_outw_pad[i] = (j < 153) ? outw[k * 153 + j] : 0.f; }
    if (i < 153 * 128) {
        int t = i / 128, j = i % 128;
        float a = 0.f;
        #pragma unroll 8
        for (int e = 0; e < 64; e++) a += emb2[t * 64 + e] * combw[e * 128 + j];
        g_tbl[i] = a;
    }
    if (i < 128 * 384) g_wh_h[i] = __float2half(wh[i]);
    if (i < 128 * 520) {
        int k = i / 520, j = i % 520;
        g_wi_h[i] = __float2half((j < 515) ? wi[k * 515 + j] : 0.f);
    }
}

struct EncP {
    const int* codes; const float* emb;
    const float *wx, *wh, *bx, *bh, *wi, *bi;
};
struct DecP {
    const int* targets;
    const float *wx, *wh, *bx, *bh, *bi;
    const float *attn0, *attn1, *combw, *combb, *outb;
    float* out;
};

// ---------------- Encoder body (R9, NB=2, wx from L2) ----------------
__device__ void enc_body(const EncP& p, float* o_out, int b0, float* sm)
{
    const int tid = threadIdx.x;
    float* s_wh = sm;               // 12288 (64x192)
    float* s_wi = s_wh + 12288;     // 16640 (64x260 padded)
    float* s_bx = s_wi + 16640;     // 192
    float* s_bh = s_bx + 192;       // 192
    float* s_bi = s_bh + 192;       // 260
    float* s_p  = s_bi + 260;       // 7680 partial union
    float* s_x  = s_p + 7680;       // 256 [k][b]  (x|r)
    float* s_h  = s_x + 256;        // 128 [j][b]
    float* s_gx = s_h + 128;        // 384
    float* s_gh = s_gx + 384;       // 384
    float* s_if = s_gh + 384;       // 520
    float* s_M  = s_if + 520;       // 2048 [b][n][e]
    float* s_mn = s_M + 2048;       // 32
    float* s_md = s_mn + 32;        // 32
    float* s_w  = s_md + 32;        // 32
    float* s_kn = s_w + 32;         // 8

    float* p_gx = s_p;              // 16 x 384
    float* p_gh = s_p + 6144;       // 4 x 384
    float* p_if = s_p;              // 8 x 520 (reuse)

    for (int i = tid; i < 12288; i += 768) s_wh[i] = p.wh[i];
    for (int i = tid; i < 16640; i += 768) {
        int k = i / 260, j = i % 260;
        s_wi[i] = (j < 259) ? p.wi[k * 259 + j] : 0.f;
    }
    if (tid < 192) { s_bx[tid] = p.bx[tid]; s_bh[tid] = p.bh[tid]; }
    if (tid < 260) s_bi[tid] = (tid < 259) ? p.bi[tid] : 0.f;
    if (tid < 256) s_x[tid] = 0.f;
    if (tid < 128) s_h[tid] = 0.f;
    for (int i = tid; i < 2048; i += 768) s_M[i] = 0.f;
    for (int i = tid; i < 1536; i += 768) p_gh[i] = 0.f;
    __syncthreads();

    const int c8 = tid & 7;
    const int pq = tid >> 3;
    const int pb = pq >> 4;
    float* Mp = s_M + pq * 64 + c8 * 8;

    if (tid < 128) {
        int b = tid & 1, e = tid >> 1;
        int code = p.codes[(b0 + b) * 512 + 0];
        s_x[e * 2 + b] = p.emb[code * 64 + e];
    }
    __syncthreads();

    for (int s = 0; s < 512; ++s) {
        // B: gx partials (wx from L2): 48 jq x 16 kq = 768 threads, 8 iters
        {
            int jq = tid % 48, kq = tid / 48;
            u64 a0 = 0, a1 = 0, a2 = 0, a3 = 0;
            const float* wb = p.wx + kq * 8 * 192 + jq * 4;
            const u64* xb = (const u64*)(s_x + kq * 16);
            #pragma unroll
            for (int i = 0; i < 8; i++) {
                float4 w = __ldg((const float4*)(wb + i * 192));
                u64 x2 = xb[i];
                fma2(a0, bc2(w.x), x2); fma2(a1, bc2(w.y), x2);
                fma2(a2, bc2(w.z), x2); fma2(a3, bc2(w.w), x2);
            }
            u64* d = (u64*)(p_gx + kq * 384 + jq * 8);
            d[0] = a0; d[1] = a1; d[2] = a2; d[3] = a3;
        }
        __syncthreads();
        // C: reduce gx (384) + gh (384)
        if (tid < 384) {
            float a = s_bx[tid >> 1];
            #pragma unroll
            for (int kq = 0; kq < 16; kq++) a += p_gx[kq * 384 + tid];
            s_gx[tid] = a;
        } else {
            int u = tid - 384;
            float g = s_bh[u >> 1];
            #pragma unroll
            for (int kh = 0; kh < 4; kh++) g += p_gh[kh * 384 + u];
            s_gh[u] = g;
        }
        __syncthreads();
        // GRU
        if (tid < 128) {
            int b = tid & 1, j = tid >> 1;
            float xr = s_gx[j*2+b], xz = s_gx[(64+j)*2+b], xn = s_gx[(128+j)*2+b];
            float hr = s_gh[j*2+b], hz = s_gh[(64+j)*2+b], hn = s_gh[(128+j)*2+b];
            float rg = sigf(xr + hr), z = sigf(xz + hz);
            float n = tanhf(xn + rg * hn);
            s_h[j*2+b] = (1.0f - z) * n + z * s_h[j*2+b];
        }
        __syncthreads();
        // iface partials: 65 jq x 8 kq = 520 threads, 8 iters
        if (tid < 520) {
            int jq = tid % 65, kq = tid / 65;
            u64 a0 = 0, a1 = 0, a2 = 0, a3 = 0;
            const float* wb = s_wi + kq * 8 * 260 + jq * 4;
            const u64* xb = (const u64*)(s_h + kq * 16);
            #pragma unroll
            for (int i = 0; i < 8; i++) {
                float4 w = *(const float4*)(wb + i * 260);
                u64 x2 = xb[i];
                fma2(a0, bc2(w.x), x2); fma2(a1, bc2(w.y), x2);
                fma2(a2, bc2(w.z), x2); fma2(a3, bc2(w.w), x2);
            }
            u64* d = (u64*)(p_if + kq * 520 + jq * 8);
            d[0] = a0; d[1] = a1; d[2] = a2; d[3] = a3;
        }
        __syncthreads();
        if (tid < 520) {
            float a = s_bi[tid >> 1];
            #pragma unroll
            for (int kq = 0; kq < 8; kq++) a += p_if[kq * 520 + tid];
            s_if[tid] = a;
        }
        __syncthreads();

        if (s < 511) {
            if (tid < 384) {
                if (tid < 256) {
                    float ss = 0.f, dw = 0.f;
                    #pragma unroll
                    for (int i = 0; i < 8; i++) {
                        float m = Mp[i];
                        ss += m * m; dw += m * s_if[(64 + c8 * 8 + i) * 2 + pb];
                    }
                    for (int d = 4; d > 0; d >>= 1) {
                        ss += __shfl_down_sync(0xffffffffu, ss, d);
                        dw += __shfl_down_sync(0xffffffffu, dw, d);
                    }
                    if (c8 == 0) { s_mn[pq] = sqrtf(ss); s_md[pq] = dw; }
                } else {
                    int w = (tid >> 5) - 8, lane = tid & 31;
                    int b = w & 1, isr = w >> 1;
                    int base = isr ? 0 : 64;
                    float v0 = s_if[(base + lane) * 2 + b], v1 = s_if[(base + 32 + lane) * 2 + b];
                    float t2 = v0 * v0 + v1 * v1;
                    for (int d = 16; d > 0; d >>= 1) t2 += __shfl_down_sync(0xffffffffu, t2, d);
                    if (lane == 0) s_kn[isr * 2 + b] = sqrtf(t2);
                }
                BARX();
                if (tid < 64 && (tid & 31) < 16) {
                    int b = tid >> 5, n = tid & 15;
                    float bw = softplusf(s_if[257*2+b]) + 1.0f;
                    float gw = sigf(s_if[258*2+b]);
                    float kn = s_kn[0*2+b];
                    float sc = bw * (s_md[b*16+n] / (s_mn[b*16+n] * kn + 1e-6f));
                    float mx = sc;
                    for (int d = 8; d > 0; d >>= 1) mx = fmaxf(mx, __shfl_xor_sync(0xffffu, mx, d));
                    float e = expf(sc - mx);
                    float sum = e;
                    for (int d = 8; d > 0; d >>= 1) sum += __shfl_xor_sync(0xffffu, sum, d);
                    s_w[b*16+n] = e * (gw / sum);
                }
                BARX();
                if (tid < 256) {
                    float wwv = s_w[pq], ss = 0.f, dr = 0.f;
                    #pragma unroll
                    for (int i = 0; i < 8; i++) {
                        int e = c8 * 8 + i;
                        float er = sigf(s_if[(128 + e) * 2 + pb]);
                        float wv = s_if[(192 + e) * 2 + pb];
                        float m = Mp[i];
                        m = m * (1.0f - wwv * er) + wwv * wv;
                        Mp[i] = m;
                        ss += m * m; dr += m * s_if[e * 2 + pb];
                    }
                    for (int d = 4; d > 0; d >>= 1) {
                        ss += __shfl_down_sync(0xffffffffu, ss, d);
                        dr += __shfl_down_sync(0xffffffffu, dr, d);
                    }
                    if (c8 == 0) { s_mn[pq] = sqrtf(ss); s_md[pq] = dr; }
                }
                BARX();
                if (tid < 64 && (tid & 31) < 16) {
                    int b = tid >> 5, n = tid & 15;
                    float br = softplusf(s_if[256*2+b]) + 1.0f;
                    float kn = s_kn[1*2+b];
                    float sc = br * (s_md[b*16+n] / (s_mn[b*16+n] * kn + 1e-6f));
                    float mx = sc;
                    for (int d = 8; d > 0; d >>= 1) mx = fmaxf(mx, __shfl_xor_sync(0xffffu, mx, d));
                    float e = expf(sc - mx);
                    float sum = e;
                    for (int d = 8; d > 0; d >>= 1) sum += __shfl_xor_sync(0xffffu, sum, d);
                    s_w[b*16+n] = e / sum;
                }
                BARX();
                if (tid < 128) {
                    int b = tid & 1, e = tid >> 1;
                    const float* Mb = s_M + b * 1024;
                    float r = 0.f;
                    #pragma unroll
                    for (int n = 0; n < 16; n++) r += s_w[b*16+n] * Mb[n * 64 + e];
                    s_x[(64 + e) * 2 + b] = r;
                    o_out[(((s >> 5) * 64 + (b0 + b)) * 32 + (s & 31)) * 64 + e] = s_h[e * 2 + b];
                }
            } else if (tid < 576) {
                int u = tid - 384;
                int jq = u % 48, kh = u / 48;
                u64 a0 = 0, a1 = 0, a2 = 0, a3 = 0;
                const float* wb = s_wh + kh * 16 * 192 + jq * 4;
                const u64* xb = (const u64*)(s_h + kh * 32);
                #pragma unroll
                for (int i = 0; i < 16; i++) {
                    float4 w = *(const float4*)(wb + i * 192);
                    u64 x2 = xb[i];
                    fma2(a0, bc2(w.x), x2); fma2(a1, bc2(w.y), x2);
                    fma2(a2, bc2(w.z), x2); fma2(a3, bc2(w.w), x2);
                }
                u64* d = (u64*)(p_gh + kh * 384 + jq * 8);
                d[0] = a0; d[1] = a1; d[2] = a2; d[3] = a3;
            } else if (tid < 704) {
                int u = tid - 576;
                int b = u & 1, e = u >> 1;
                int code = p.codes[(b0 + b) * 512 + (s + 1)];
                s_x[e * 2 + b] = p.emb[code * 64 + e];
            }
            __syncthreads();
        } else {
            if (tid < 128) {
                int b = tid & 1, e = tid >> 1;
                o_out[(((s >> 5) * 64 + (b0 + b)) * 32 + (s & 31)) * 64 + e] = s_h[e * 2 + b];
            }
            __syncthreads();
        }
        if ((s & 31) == 31) {
            __threadfence();
            if (tid == 0) atomicExch(&g_prog[blockIdx.x], (s >> 5) + 1);
        }
    }
}

// ---------------- Decoder body (NB=2, fp16 wh/wi streams) ----------------
__device__ void dec_body(const DecP& p, int jj, float* sm)
{
    const int b0 = jj * 2;
    const int tid = threadIdx.x;

    float* s_ow = sm;            // 19968 (128x156) outw h-half cache
    float* s_p  = s_ow + 19968;  // 12288 partial union
    float* s_x  = s_p + 12288;   // 512
    float* s_h  = s_x + 512;     // 256
    float* s_gx = s_h + 256;     // 768
    float* s_gh = s_gx + 768;    // 768
    float* s_if = s_gh + 768;    // 1040
    float* s_M  = s_if + 1040;   // 4096
    float* s_c  = s_M + 4096;    // 256
    float* s_cc = s_c + 256;     // 256
    float* s_oc = s_cc + 256;    // 312
    float* s_at = s_oc + 312;    // 128
    float* s_mn = s_at + 128;    // 32
    float* s_md = s_mn + 32;     // 32
    float* s_w  = s_md + 32;     // 32
    float* s_kn = s_w + 32;      // 8
    float* s_bx2 = s_kn + 8;     // 384
    float* s_bh2 = s_bx2 + 384;  // 384
    float* s_bi2 = s_bh2 + 384;  // 520

    float* p_wx = s_p;           // 8 x 768  [0..6144)
    float* p_wh = s_p + 6144;    // 8 x 768  [6144..12288)
    float* p_if = s_p;           // 8 x 1040 [0..8320)
    float* p_oh = s_p + 8320;    // 4 x 312  [8320..9568)
    float* p_cb = s_p;           // 4 x 256 (per-v)
    float* p_oc = s_p + 1024;    // 4 x 312 (per-v)

    for (int i = tid; i < 19968; i += 768) s_ow[i] = g_outw_pad[i];
    for (int i = tid; i < 512; i += 768) s_x[i] = 0.f;
    for (int i = tid; i < 4096; i += 768) s_M[i] = 0.f;
    if (tid < 384) { s_bx2[tid] = p.bx[tid]; s_bh2[tid] = p.bh[tid]; }
    if (tid < 520) s_bi2[tid] = (tid < 515) ? p.bi[tid] : 0.f;
    __syncthreads();

    if (tid == 0) {
        while (*(volatile int*)&g_prog[jj] < 1 || *(volatile int*)&g_prog[32 + jj] < 1)
            __nanosleep(200);
    }
    __syncthreads();
    if (tid < 256) {
        int b = tid & 1, e = tid >> 1;
        float h = (e < 64) ? g_o1[((b0 + b) * 32 + 31) * 64 + e]
                           : g_o2[((b0 + b) * 32 + 31) * 64 + (e - 64)];
        s_h[e * 2 + b] = h;
    }
    __syncthreads();

    const int c8 = tid & 7;
    const int pq = tid >> 3;
    const int pb = pq >> 4;
    float* Mp = s_M + pq * 128 + c8 * 16;

    for (int s = 0; s < 400; ++s) {
        const int v = s / 25, pos = s - v * 25;

        if (pos == 0) {
            if (tid == 0) {
                while (*(volatile int*)&g_prog[jj] <= v || *(volatile int*)&g_prog[32 + jj] <= v)
                    __nanosleep(200);
            }
            __syncthreads();
            // V0: attention scores
            if (tid < 256) {
                int cc = tid & 1, g = tid >> 1;
                int a = g >> 6, b = (g >> 5) & 1, l = g & 31;
                const float* op = (a ? g_o2 : g_o1) + ((v * 64 + (b0 + b)) * 32 + l) * 64 + cc * 32;
                const float* aw = (a ? p.attn1 : p.attn0) + 128 + cc * 32;
                float sc = 0.f;
                #pragma unroll
                for (int e = 0; e < 32; e++) sc += op[e] * __ldg(aw + e);
                sc += __shfl_down_sync(0xffffffffu, sc, 1);
                if (cc == 0) s_at[g] = sc;
            }
            __syncthreads();
            // V1: softmax
            if (tid < 128) {
                int w = tid >> 5, l = tid & 31;
                float vsc = s_at[w * 32 + l];
                float mx = vsc;
                for (int d = 16; d > 0; d >>= 1) mx = fmaxf(mx, __shfl_xor_sync(0xffffffffu, mx, d));
                float e2 = expf(vsc - mx);
                float sum = e2;
                for (int d = 16; d > 0; d >>= 1) sum += __shfl_xor_sync(0xffffffffu, sum, d);
                s_at[w * 32 + l] = e2 / sum;
            }
            __syncthreads();
            // V2: contexts
            if (tid < 256) {
                int a = tid >> 7, b = (tid >> 6) & 1, e = tid & 63;
                const float* op = (a ? g_o2 : g_o1) + ((v * 64 + (b0 + b)) * 32) * 64 + e;
                const float* at = s_at + a * 64 + b * 32;
                float cv = 0.f;
                #pragma unroll
                for (int l = 0; l < 32; l++) cv += at[l] * op[l * 64];
                s_c[(a * 64 + e) * 2 + b] = cv;
            }
            __syncthreads();
            // V3: comb_cc + out_cc partials
            if (tid < 128) {
                int jq = tid & 31, kq = tid >> 5;
                u64 a0 = 0, a1 = 0, a2 = 0, a3 = 0;
                const float* wb = p.combw + (64 + kq * 32) * 128 + jq * 4;
                const u64* xb = (const u64*)(s_c + kq * 64);
                #pragma unroll
                for (int i = 0; i < 32; i++) {
                    float4 w = __ldg((const float4*)(wb + i * 128));
                    u64 x2 = xb[i];
                    fma2(a0, bc2(w.x), x2); fma2(a1, bc2(w.y), x2);
                    fma2(a2, bc2(w.z), x2); fma2(a3, bc2(w.w), x2);
                }
                u64* d = (u64*)(p_cb + kq * 256 + jq * 8);
                d[0] = a0; d[1] = a1; d[2] = a2; d[3] = a3;
            } else if (tid < 284) {
                int u = tid - 128;
                int jq = u % 39, kq = u / 39;
                u64 a0 = 0, a1 = 0, a2 = 0, a3 = 0;
                const float* wb = g_outw_pad + (128 + kq * 32) * 156 + jq * 4;
                const u64* xb = (const u64*)(s_c + kq * 64);
                #pragma unroll
                for (int i = 0; i < 32; i++) {
                    float4 w = *(const float4*)(wb + i * 156);
                    u64 x2 = xb[i];
                    fma2(a0, bc2(w.x), x2); fma2(a1, bc2(w.y), x2);
                    fma2(a2, bc2(w.z), x2); fma2(a3, bc2(w.w), x2);
                }
                u64* d = (u64*)(p_oc + kq * 312 + jq * 8);
                d[0] = a0; d[1] = a1; d[2] = a2; d[3] = a3;
            }
            __syncthreads();
            // V4: reduce
            if (tid < 256) {
                float a = __ldg(p.combb + (tid >> 1));
                #pragma unroll
                for (int kq = 0; kq < 4; kq++) a += p_cb[kq * 256 + tid];
                s_cc[tid] = a;
            } else if (tid < 568) {
                int idx = tid - 256;
                int j = idx >> 1;
                float a = (j < 153) ? __ldg(p.outb + j) : 0.f;
                #pragma unroll
                for (int kq = 0; kq < 4; kq++) a += p_oc[kq * 312 + idx];
                s_oc[idx] = a;
            }
            __syncthreads();
            // A-inline: comb (start/split token) + wh partials (fp16, 8-j span)
            if (tid < 256) {
                int tok = (v == 0) ? 150 : 151;
                s_x[tid] = fmaxf(__ldg(g_tbl + tok * 128 + (tid >> 1)) + s_cc[tid], 0.f);
            } else if (tid < 640) {
                int u = tid - 256;
                int jq = u % 48, kq = u / 48;   // 8 kq x 16 k
                gemv_h8<16, 384>(g_wh_h + kq * 16 * 384 + jq * 8,
                                 s_h + kq * 32, p_wh + kq * 768 + jq * 16);
            }
            __syncthreads();
        }

        // B: wx partials: 96 jq x 8 kq = 768 threads, 32 iters (fp32)
        {
            int jq = tid % 96, kq = tid / 96;
            u64 a0 = 0, a1 = 0, a2 = 0, a3 = 0;
            const float* wb = p.wx + kq * 32 * 384 + jq * 4;
            const u64* xb = (const u64*)(s_x + kq * 64);
            #pragma unroll
            for (int i = 0; i < 32; i++) {
                float4 w = __ldg((const float4*)(wb + i * 384));
                u64 x2 = xb[i];
                fma2(a0, bc2(w.x), x2); fma2(a1, bc2(w.y), x2);
                fma2(a2, bc2(w.z), x2); fma2(a3, bc2(w.w), x2);
            }
            u64* d = (u64*)(p_wx + kq * 768 + jq * 8);
            d[0] = a0; d[1] = a1; d[2] = a2; d[3] = a3;
        }
        __syncthreads();
        // C1: reduce gx (8 partials) / gh (8 partials)
        {
            float a = s_bx2[tid >> 1];
            float g = s_bh2[tid >> 1];
            #pragma unroll
            for (int kq = 0; kq < 8; kq++) {
                a += p_wx[kq * 768 + tid];
                g += p_wh[kq * 768 + tid];
            }
            s_gx[tid] = a; s_gh[tid] = g;
        }
        __syncthreads();
        // C2: GRU
        if (tid < 256) {
            int b = tid & 1, j = tid >> 1;
            float xr = s_gx[j*2+b], xz = s_gx[(128+j)*2+b], xn = s_gx[(256+j)*2+b];
            float hr = s_gh[j*2+b], hz = s_gh[(128+j)*2+b], hn = s_gh[(256+j)*2+b];
            float rg = sigf(xr + hr), z = sigf(xz + hz);
            float n = tanhf(xn + rg * hn);
            s_h[j*2+b] = (1.0f - z) * n + z * s_h[j*2+b];
        }
        __syncthreads();
        // D: wi (fp16, 8-j span: 65 jq x 8 kq, 16 iters) + outw_h (smem) partials
        if (tid < 520) {
            int jq = tid % 65, kq = tid / 65;
            gemv_h8<16, 520>(g_wi_h + kq * 16 * 520 + jq * 8,
                             s_h + kq * 32, p_if + kq * 1040 + jq * 16);
        } else if (tid < 676) {
            int u = tid - 520;
            int jq = u % 39, kq = u / 39;
            u64 a0 = 0, a1 = 0, a2 = 0, a3 = 0;
            const float* wb = s_ow + kq * 32 * 156 + jq * 4;
            const u64* xb = (const u64*)(s_h + kq * 64);
            #pragma unroll
            for (int i = 0; i < 32; i++) {
                float4 w = *(const float4*)(wb + i * 156);
                u64 x2 = xb[i];
                fma2(a0, bc2(w.x), x2); fma2(a1, bc2(w.y), x2);
                fma2(a2, bc2(w.z), x2); fma2(a3, bc2(w.w), x2);
            }
            u64* d = (u64*)(p_oh + kq * 312 + jq * 8);
            d[0] = a0; d[1] = a1; d[2] = a2; d[3] = a3;
        }
        __syncthreads();
        // E: reduce iface (8 partials over 1040) + logits store
        for (int u = tid; u < 1040; u += 768) {
            float a = s_bi2[u >> 1];
            #pragma unroll
            for (int kq = 0; kq < 8; kq++) a += p_if[kq * 1040 + u];
            s_if[u] = a;
        }
        if (tid < 306) {
            int j = tid >> 1, b = tid & 1;
            float a = s_oc[tid];
            #pragma unroll
            for (int kq = 0; kq < 4; kq++) a += p_oh[kq * 312 + tid];
            p.out[((b0 + b) * 400 + s) * 153 + j] = a;
        }
        __syncthreads();

        if (pos < 24) {
            if (tid < 384) {
                if (tid < 256) {
                    float ss = 0.f, dw = 0.f;
                    #pragma unroll
                    for (int i = 0; i < 16; i++) {
                        float m = Mp[i];
                        ss += m * m; dw += m * s_if[(128 + c8 * 16 + i) * 2 + pb];
                    }
                    for (int d = 4; d > 0; d >>= 1) {
                        ss += __shfl_down_sync(0xffffffffu, ss, d);
                        dw += __shfl_down_sync(0xffffffffu, dw, d);
                    }
                    if (c8 == 0) { s_mn[pq] = sqrtf(ss); s_md[pq] = dw; }
                } else {
                    int w = (tid >> 5) - 8, lane = tid & 31;
                    int b = w & 1, isr = w >> 1;
                    int base = isr ? 0 : 128;
                    float t2 = 0.f;
                    #pragma unroll
                    for (int q = 0; q < 4; q++) {
                        float vq = s_if[(base + lane + q * 32) * 2 + b];
                        t2 += vq * vq;
                    }
                    for (int d = 16; d > 0; d >>= 1) t2 += __shfl_down_sync(0xffffffffu, t2, d);
                    if (lane == 0) s_kn[isr * 2 + b] = sqrtf(t2);
                }
                BARX();
                if (tid < 64) {
                    if ((tid & 31) < 16) {
                        int b = tid >> 5, n = tid & 15;
                        float bw = softplusf(s_if[513*2+b]) + 1.0f;
                        float gw = sigf(s_if[514*2+b]);
                        float kn = s_kn[0*2+b];
                        float sc = bw * (s_md[b*16+n] / (s_mn[b*16+n] * kn + 1e-6f));
                        float mx = sc;
                        for (int d = 8; d > 0; d >>= 1) mx = fmaxf(mx, __shfl_xor_sync(0xffffu, mx, d));
                        float e = expf(sc - mx);
                        float sum = e;
                        for (int d = 8; d > 0; d >>= 1) sum += __shfl_xor_sync(0xffffu, sum, d);
                        s_w[b*16+n] = e * (gw / sum);
                    }
                } else if (tid < 320) {
                    int idx = tid - 64;
                    int b = idx & 1, j = idx >> 1;
                    int tok = p.targets[((b0 + b) * 16 + v) * 24 + pos];
                    s_x[idx] = fmaxf(__ldg(g_tbl + tok * 128 + j) + s_cc[idx], 0.f);
                }
                BARX();
                if (tid < 256) {
                    float wwv = s_w[pq], ss = 0.f, dr = 0.f;
                    #pragma unroll
                    for (int i = 0; i < 16; i++) {
                        int e = c8 * 16 + i;
                        float er = sigf(s_if[(256 + e) * 2 + pb]);
                        float wv = s_if[(384 + e) * 2 + pb];
                        float m = Mp[i];
                        m = m * (1.0f - wwv * er) + wwv * wv;
                        Mp[i] = m;
                        ss += m * m; dr += m * s_if[e * 2 + pb];
                    }
                    for (int d = 4; d > 0; d >>= 1) {
                        ss += __shfl_down_sync(0xffffffffu, ss, d);
                        dr += __shfl_down_sync(0xffffffffu, dr, d);
                    }
                    if (c8 == 0) { s_mn[pq] = sqrtf(ss); s_md[pq] = dr; }
                }
                BARX();
                if (tid < 64 && (tid & 31) < 16) {
                    int b = tid >> 5, n = tid & 15;
                    float br = softplusf(s_if[512*2+b]) + 1.0f;
                    float kn = s_kn[1*2+b];
                    float sc = br * (s_md[b*16+n] / (s_mn[b*16+n] * kn + 1e-6f));
                    float mx = sc;
                    for (int d = 8; d > 0; d >>= 1) mx = fmaxf(mx, __shfl_xor_sync(0xffffu, mx, d));
                    float e = expf(sc - mx);
                    float sum = e;
                    for (int d = 8; d > 0; d >>= 1) sum += __shfl_xor_sync(0xffffu, sum, d);
                    s_w[b*16+n] = e / sum;
                }
                BARX();
                if (tid < 256) {
                    int b = tid & 1, e = tid >> 1;
                    const float* Mb = s_M + b * 2048;
                    float r = 0.f;
                    #pragma unroll
                    for (int n = 0; n < 16; n++) r += s_w[b*16+n] * Mb[n * 128 + e];
                    s_x[(128 + e) * 2 + b] = r;
                }
            } else {
                // Y: next-step wh partials (fp16, 8-j span): 48 jq x 8 kq, 16 iters
                int u = tid - 384;
                int jq = u % 48, kq = u / 48;
                gemv_h8<16, 384>(g_wh_h + kq * 16 * 384 + jq * 8,
                                 s_h + kq * 32, p_wh + kq * 768 + jq * 16);
            }
            __syncthreads();
        } else if (s < 399) {
            // serial tail at tile boundary
            if (tid < 256) {
                float ss = 0.f, dw = 0.f;
                #pragma unroll
                for (int i = 0; i < 16; i++) {
                    float m = Mp[i];
                    ss += m * m; dw += m * s_if[(128 + c8 * 16 + i) * 2 + pb];
                }
                for (int d = 4; d > 0; d >>= 1) {
                    ss += __shfl_down_sync(0xffffffffu, ss, d);
                    dw += __shfl_down_sync(0xffffffffu, dw, d);
                }
                if (c8 == 0) { s_mn[pq] = sqrtf(ss); s_md[pq] = dw; }
            } else if (tid < 384) {
                int w = (tid >> 5) - 8, lane = tid & 31;
                int b = w & 1, isr = w >> 1;
                int base = isr ? 0 : 128;
                float t2 = 0.f;
                #pragma unroll
                for (int q = 0; q < 4; q++) {
                    float vq = s_if[(base + lane + q * 32) * 2 + b];
                    t2 += vq * vq;
                }
                for (int d = 16; d > 0; d >>= 1) t2 += __shfl_down_sync(0xffffffffu, t2, d);
                if (lane == 0) s_kn[isr * 2 + b] = sqrtf(t2);
            }
            __syncthreads();
            if (tid < 64 && (tid & 31) < 16) {
                int b = tid >> 5, n = tid & 15;
                float bw = softplusf(s_if[513*2+b]) + 1.0f;
                float gw = sigf(s_if[514*2+b]);
                float kn = s_kn[0*2+b];
                float sc = bw * (s_md[b*16+n] / (s_mn[b*16+n] * kn + 1e-6f));
                float mx = sc;
                for (int d = 8; d > 0; d >>= 1) mx = fmaxf(mx, __shfl_xor_sync(0xffffu, mx, d));
                float e = expf(sc - mx);
                float sum = e;
                for (int d = 8; d > 0; d >>= 1) sum += __shfl_xor_sync(0xffffu, sum, d);
                s_w[b*16+n] = e * (gw / sum);
            }
            __syncthreads();
            if (tid < 256) {
                float wwv = s_w[pq], ss = 0.f, dr = 0.f;
                #pragma unroll
                for (int i = 0; i < 16; i++) {
                    int e = c8 * 16 + i;
                    float er = sigf(s_if[(256 + e) * 2 + pb]);
                    float wv = s_if[(384 + e) * 2 + pb];
                    float m = Mp[i];
                    m = m * (1.0f - wwv * er) + wwv * wv;
                    Mp[i] = m;
                    ss += m * m; dr += m * s_if[e * 2 + pb];
                }
                for (int d = 4; d > 0; d >>= 1) {
                    ss += __shfl_down_sync(0xffffffffu, ss, d);
                    dr += __shfl_down_sync(0xffffffffu, dr, d);
                }
                if (c8 == 0) { s_mn[pq] = sqrtf(ss); s_md[pq] = dr; }
            }
            __syncthreads();
            if (tid < 64 && (tid & 31) < 16) {
                int b = tid >> 5, n = tid & 15;
                float br = softplusf(s_if[512*2+b]) + 1.0f;
                float kn = s_kn[1*2+b];
                float sc = br * (s_md[b*16+n] / (s_mn[b*16+n] * kn + 1e-6f));
                float mx = sc;
                for (int d = 8; d > 0; d >>= 1) mx = fmaxf(mx, __shfl_xor_sync(0xffffu, mx, d));
                float e = expf(sc - mx);
                float sum = e;
                for (int d = 8; d > 0; d >>= 1) sum += __shfl_xor_sync(0xffffu, sum, d);
                s_w[b*16+n] = e / sum;
            }
            __syncthreads();
            if (tid < 256) {
                int b = tid & 1, e = tid >> 1;
                const float* Mb = s_M + b * 2048;
                float r = 0.f;
                #pragma unroll
                for (int n = 0; n < 16; n++) r += s_w[b*16+n] * Mb[n * 128 + e];
                s_x[(128 + e) * 2 + b] = r;
            }
            __syncthreads();
        }
    }
}

__global__ void __launch_bounds__(768, 1)
fused_kernel(EncP P0, EncP P1, DecP D)
{
    extern __shared__ float sm[];
    int bid = blockIdx.x;
    if (bid < 64) {
        const EncP& p = (bid < 32) ? P0 : P1;
        float* o_out = (bid < 32) ? g_o1 : g_o2;
        enc_body(p, o_out, (bid & 31) * 2, sm);
    } else {
        dec_body(D, bid - 64, sm);
    }
}

// ======= labels + tail copies =======
__global__ void tail_kernel(const int* __restrict__ targets, float* __restrict__ out)
{
    int idx = blockIdx.x * blockDim.x + threadIdx.x;
    if (idx < 25600) {
        int b = idx / 400, ss = idx % 400;
        int t = ss / 25, j = ss % 25;
        float val = (j < 24) ? (float)targets[(b * 16 + t) * 24 + j]
                             : ((t == 15) ? 152.0f : 151.0f);
        out[3916800 + idx] = val;
        if (ss >= 375) out[4187200 + b * 25 + (ss - 375)] = val;
    }
    if (idx < 244800) {
        int b = idx / 3825, rem = idx % 3825;
        out[3942400 + idx] = out[(b * 400 + 375) * 153 + rem];
    }
}

extern "C" void kernel_launch(void* const* d_in, const int* in_sizes, int n_in,
                              void* d_out, int out_size)
{
    (void)in_sizes; (void)n_in; (void)out_size;
    const int*   codes1 = (const int*)d_in[0];
    const int*   codes2 = (const int*)d_in[1];
    const int*   targets= (const int*)d_in[2];

    EncP P0 { codes1, (const float*)d_in[3], (const float*)d_in[6],  (const float*)d_in[7],
              (const float*)d_in[8],  (const float*)d_in[9],
              (const float*)d_in[10], (const float*)d_in[11] };
    EncP P1 { codes2, (const float*)d_in[4], (const float*)d_in[12], (const float*)d_in[13],
              (const float*)d_in[14], (const float*)d_in[15],
              (const float*)d_in[16], (const float*)d_in[17] };
    DecP D  { targets,
              (const float*)d_in[18], (const float*)d_in[19],
              (const float*)d_in[20], (const float*)d_in[21],
              (const float*)d_in[23],
              (const float*)d_in[24], (const float*)d_in[25],
              (const float*)d_in[26], (const float*)d_in[27],
              (const float*)d_in[29],
              (float*)d_out };

    static bool attr_done = false;
    if (!attr_done) {
        cudaFuncSetAttribute(fused_kernel, cudaFuncAttributeMaxDynamicSharedMemorySize, 170000);
        attr_done = true;
    }

    prep_kernel<<<260, 256>>>((const float*)d_in[22], (const float*)d_in[28],
                              (const float*)d_in[5], (const float*)d_in[26],
                              (const float*)d_in[19]);
    fused_kernel<<<96, 768, 170000>>>(P0, P1, D);
    tail_kernel<<<(244800 + 255) / 256, 256>>>(targets, (float*)d_out);
}